// round 10
// baseline (speedup 1.0000x reference)
#include <cuda_runtime.h>
#include <math.h>
#include <stdint.h>

// Problem constants
#define Bz   2
#define Lz   2048
#define Ez   1024
#define Hz   16
#define Dz   64
#define BLz  (Bz*Lz)          // 4096 rows
#define E3z  (3*Ez)           // 3072
#define FFz  (4*Ez)           // 4096

// ---------------- static device scratch (no allocations allowed) ----------------
__device__ float g_h    [(size_t)BLz*Ez];
__device__ float g_qkv  [(size_t)BLz*E3z];
__device__ float g_att  [(size_t)BLz*Ez];
__device__ float g_x1   [(size_t)BLz*Ez];
__device__ float g_ffn  [(size_t)BLz*FFz];
__device__ float g_wqkvT[(size_t)E3z*Ez];
__device__ float g_wprojT[(size_t)Ez*Ez];
__device__ float g_w1T  [(size_t)FFz*Ez];
__device__ float g_w2T  [(size_t)Ez*FFz];
__device__ float g_vT   [(size_t)Bz*Hz*Dz*Lz];

// ---------------- helpers ----------------
static __device__ __forceinline__ float tf32r(float x) {
    uint32_t r;
    asm("cvt.rna.tf32.f32 %0, %1;" : "=r"(r) : "f"(x));
    return __uint_as_float(r);
}
static __device__ __forceinline__ void mma_tf32(
    float* c, const float* a, const float* b)
{
    asm volatile(
        "mma.sync.aligned.m16n8k8.row.col.f32.tf32.tf32.f32 "
        "{%0,%1,%2,%3}, {%4,%5,%6,%7}, {%8,%9}, {%0,%1,%2,%3};"
        : "+f"(c[0]), "+f"(c[1]), "+f"(c[2]), "+f"(c[3])
        : "r"(__float_as_uint(a[0])), "r"(__float_as_uint(a[1])),
          "r"(__float_as_uint(a[2])), "r"(__float_as_uint(a[3])),
          "r"(__float_as_uint(b[0])), "r"(__float_as_uint(b[1])));
}
#define CP16(dst_u32, src_ptr) \
    asm volatile("cp.async.ca.shared.global [%0], [%1], 16;" \
                 :: "r"(dst_u32), "l"(src_ptr))
#define CP_COMMIT()  asm volatile("cp.async.commit_group;" ::: "memory")
#define CP_WAIT1()   asm volatile("cp.async.wait_group 1;" ::: "memory")
#define CP_WAIT0()   asm volatile("cp.async.wait_group 0;" ::: "memory")

// ---------------- tf32 mma.sync GEMM: 128 x BN tile, BK=32, 256 threads ----------------
// cp.async double-buffered smem (raw fp32), tf32 RNA conversion at fragment load.
// A: [M,K] K-major (lda), B: [N,K] K-major (ldb), C: [M,N] (ldc).
enum { EPI_NONE = 0, EPI_BIAS_RES = 1, EPI_BIAS_GELU = 2 };

#define SLD 36   // smem row stride in floats (conflict-free fragment reads)

template<int BN, int EPI>
__global__ void __launch_bounds__(256, 2)
mma_gemm(const float* __restrict__ A, const float* __restrict__ B, float* __restrict__ C,
         const float* __restrict__ bias, const float* __restrict__ res,
         int K, int lda, int ldb, int ldc, int NH,
         long long sAb, long long sAh, long long sBb, long long sBh,
         long long sCb, long long sCh)
{
    constexpr int WN  = BN / 4;
    constexpr int NT  = WN / 8;
    constexpr int PBn = BN / 32;

    extern __shared__ float sm[];
    float* Asm = sm;                       // 2 x 128 x SLD
    float* Bsm = sm + 2 * 128 * SLD;       // 2 x BN x SLD

    int tid  = threadIdx.x;
    int lane = tid & 31;
    int wid  = tid >> 5;
    int warp_m = wid & 1;
    int warp_n = wid >> 1;

    int z = blockIdx.z;
    int bb = z / NH, hh = z % NH;
    A += bb * sAb + hh * sAh;
    B += bb * sBb + hh * sBh;
    C += bb * sCb + hh * sCh;
    const float* resp = (EPI == EPI_BIAS_RES) ? (res + bb * sCb + hh * sCh) : res;

    int m0 = blockIdx.y * 128;
    int n0 = blockIdx.x * BN;

    uint32_t As_u = (uint32_t)__cvta_generic_to_shared(Asm);
    uint32_t Bs_u = (uint32_t)__cvta_generic_to_shared(Bsm);

    float acc[4][NT][4];
    #pragma unroll
    for (int i = 0; i < 4; i++)
        #pragma unroll
        for (int j = 0; j < NT; j++)
            #pragma unroll
            for (int k = 0; k < 4; k++) acc[i][j][k] = 0.f;

    const int slabs = K >> 5;

    auto issue = [&](int s, int b) {
        int k0 = s << 5;
        #pragma unroll
        for (int i = 0; i < 4; i++) {
            int e = tid + i * 256, row = e >> 3, c4 = e & 7;
            CP16(As_u + (uint32_t)(b * 128 * SLD + row * SLD + c4 * 4) * 4,
                 &A[(long long)(m0 + row) * lda + k0 + c4 * 4]);
        }
        #pragma unroll
        for (int i = 0; i < PBn; i++) {
            int e = tid + i * 256, row = e >> 3, c4 = e & 7;
            CP16(Bs_u + (uint32_t)(b * BN * SLD + row * SLD + c4 * 4) * 4,
                 &B[(long long)(n0 + row) * ldb + k0 + c4 * 4]);
        }
    };

    issue(0, 0);
    CP_COMMIT();

    int qr = lane >> 2, qc = lane & 3;
    for (int s = 0; s < slabs; s++) {
        if (s + 1 < slabs) {
            issue(s + 1, (s + 1) & 1);
            CP_COMMIT();
            CP_WAIT1();
        } else {
            CP_WAIT0();
        }
        __syncthreads();

        const float* Ab = Asm + (s & 1) * 128 * SLD;
        const float* Bb = Bsm + (s & 1) * BN * SLD;

        #pragma unroll
        for (int ks = 0; ks < 4; ks++) {
            int kk = ks * 8;
            float af[4][4];
            #pragma unroll
            for (int mt = 0; mt < 4; mt++) {
                int r = warp_m * 64 + mt * 16 + qr;
                af[mt][0] = tf32r(Ab[r * SLD + kk + qc]);
                af[mt][1] = tf32r(Ab[(r + 8) * SLD + kk + qc]);
                af[mt][2] = tf32r(Ab[r * SLD + kk + 4 + qc]);
                af[mt][3] = tf32r(Ab[(r + 8) * SLD + kk + 4 + qc]);
            }
            float bf[NT][2];
            #pragma unroll
            for (int nt = 0; nt < NT; nt++) {
                int cN = warp_n * WN + nt * 8 + qr;
                bf[nt][0] = tf32r(Bb[cN * SLD + kk + qc]);
                bf[nt][1] = tf32r(Bb[cN * SLD + kk + 4 + qc]);
            }
            #pragma unroll
            for (int mt = 0; mt < 4; mt++)
                #pragma unroll
                for (int nt = 0; nt < NT; nt++)
                    mma_tf32(acc[mt][nt], af[mt], bf[nt]);
        }
        __syncthreads();
    }

    #pragma unroll
    for (int mt = 0; mt < 4; mt++) {
        #pragma unroll
        for (int nt = 0; nt < NT; nt++) {
            int gc = n0 + warp_n * WN + nt * 8 + qc * 2;
            #pragma unroll
            for (int half = 0; half < 2; half++) {
                long long gr = m0 + warp_m * 64 + mt * 16 + qr + half * 8;
                float v0 = acc[mt][nt][half * 2 + 0];
                float v1 = acc[mt][nt][half * 2 + 1];
                if (EPI == EPI_BIAS_RES) {
                    v0 += bias[gc]     + resp[gr * ldc + gc];
                    v1 += bias[gc + 1] + resp[gr * ldc + gc + 1];
                }
                if (EPI == EPI_BIAS_GELU) {
                    v0 += bias[gc];
                    v1 += bias[gc + 1];
                    v0 = 0.5f * v0 * (1.f + erff(v0 * 0.70710678118654752f));
                    v1 = 0.5f * v1 * (1.f + erff(v1 * 0.70710678118654752f));
                }
                *reinterpret_cast<float2*>(&C[gr * ldc + gc]) = make_float2(v0, v1);
            }
        }
    }
}

// ---------------- fused flash attention, 64-key tiles, 2 CTAs/SM ----------------
// Grid: (Lz/128, Bz*Hz). 256 threads. One CTA = one (head, 128-query tile).
#define QLD 68    // smem stride for all tiles (68 % 32 == 4, conflict-free)

__global__ void __launch_bounds__(256, 2)
flash_k(const float* __restrict__ qkv, const float* __restrict__ vT,
        float* __restrict__ att)
{
    extern __shared__ float sm[];
    float* Qs   = sm;                    // 128 x QLD
    float* Ks   = Qs + 128 * QLD;        // 64  x QLD  (keys x dims)
    float* Vs   = Ks + 64 * QLD;         // 64  x QLD  (dims x keys)
    float* Ss   = Vs + 64 * QLD;         // 128 x QLD
    float* rowm = Ss + 128 * QLD;        // 128
    float* rowl = rowm + 128;            // 128
    float* rowf = rowl + 128;            // 128

    int tid  = threadIdx.x;
    int lane = tid & 31;
    int wid  = tid >> 5;
    int qr = lane >> 2, qc = lane & 3;
    int warp_m = wid >> 1;               // 0..3 : 32 query rows each
    int warp_n = wid & 1;                // 0..1 : 32 cols each

    int bb = blockIdx.y >> 4;            // Hz = 16
    int hh = blockIdx.y & 15;
    int q0 = blockIdx.x * 128;
    const float CEXP = 1.4426950408889634f / 32.f;   // log2(e)/sqrt(E)

    const float* Qg = qkv + (size_t)bb * Lz * E3z + hh * Dz;
    const float* Kg = qkv + (size_t)bb * Lz * E3z + Ez + hh * Dz;
    const float* Vg = vT + ((size_t)(bb * Hz + hh)) * Dz * Lz;

    // load Q tile (128 x 64), tf32-rounded
    #pragma unroll
    for (int i = 0; i < 8; i++) {
        int e = tid + i * 256, row = e >> 4, c4 = e & 15;
        float4 v = *reinterpret_cast<const float4*>(&Qg[(size_t)(q0 + row) * E3z + c4 * 4]);
        float4 u = make_float4(tf32r(v.x), tf32r(v.y), tf32r(v.z), tf32r(v.w));
        *reinterpret_cast<float4*>(&Qs[row * QLD + c4 * 4]) = u;
    }
    if (tid < 128) { rowm[tid] = -INFINITY; rowl[tid] = 0.f; }

    float o[2][4][4];
    #pragma unroll
    for (int mt = 0; mt < 2; mt++)
        #pragma unroll
        for (int nt = 0; nt < 4; nt++)
            #pragma unroll
            for (int k = 0; k < 4; k++) o[mt][nt][k] = 0.f;

    for (int kt = 0; kt < 32; kt++) {
        __syncthreads();    // prev PV reads of Ks/Vs/Ss done; Q visible on iter 0

        // fill K tile (64 keys x 64 dims)
        #pragma unroll
        for (int i = 0; i < 4; i++) {
            int e = tid + i * 256, row = e >> 4, c4 = e & 15;
            float4 v = *reinterpret_cast<const float4*>(
                &Kg[(size_t)(kt * 64 + row) * E3z + c4 * 4]);
            float4 u = make_float4(tf32r(v.x), tf32r(v.y), tf32r(v.z), tf32r(v.w));
            *reinterpret_cast<float4*>(&Ks[row * QLD + c4 * 4]) = u;
        }
        // fill V tile (64 dims x 64 keys), dim-major from vT
        #pragma unroll
        for (int i = 0; i < 4; i++) {
            int e = tid + i * 256, row = e >> 4, c4 = e & 15;
            float4 v = *reinterpret_cast<const float4*>(
                &Vg[(size_t)row * Lz + kt * 64 + c4 * 4]);
            float4 u = make_float4(tf32r(v.x), tf32r(v.y), tf32r(v.z), tf32r(v.w));
            *reinterpret_cast<float4*>(&Vs[row * QLD + c4 * 4]) = u;
        }
        __syncthreads();

        // ---- S = Q @ K^T (this warp: 32 rows x 32 cols) ----
        float sqk[2][4][4];
        #pragma unroll
        for (int mt = 0; mt < 2; mt++)
            #pragma unroll
            for (int nt = 0; nt < 4; nt++)
                #pragma unroll
                for (int k = 0; k < 4; k++) sqk[mt][nt][k] = 0.f;

        #pragma unroll
        for (int ks = 0; ks < 8; ks++) {
            int kk = ks * 8;
            float af[2][4];
            #pragma unroll
            for (int mt = 0; mt < 2; mt++) {
                int r = warp_m * 32 + mt * 16 + qr;
                af[mt][0] = Qs[r * QLD + kk + qc];
                af[mt][1] = Qs[(r + 8) * QLD + kk + qc];
                af[mt][2] = Qs[r * QLD + kk + 4 + qc];
                af[mt][3] = Qs[(r + 8) * QLD + kk + 4 + qc];
            }
            float bf[4][2];
            #pragma unroll
            for (int nt = 0; nt < 4; nt++) {
                int cN = warp_n * 32 + nt * 8 + qr;
                bf[nt][0] = Ks[cN * QLD + kk + qc];
                bf[nt][1] = Ks[cN * QLD + kk + 4 + qc];
            }
            #pragma unroll
            for (int mt = 0; mt < 2; mt++)
                #pragma unroll
                for (int nt = 0; nt < 4; nt++)
                    mma_tf32(sqk[mt][nt], af[mt], bf[nt]);
        }
        // spill S fragments to smem
        #pragma unroll
        for (int mt = 0; mt < 2; mt++) {
            int r = warp_m * 32 + mt * 16 + qr;
            #pragma unroll
            for (int nt = 0; nt < 4; nt++) {
                int c = warp_n * 32 + nt * 8 + qc * 2;
                Ss[r * QLD + c]           = sqk[mt][nt][0];
                Ss[r * QLD + c + 1]       = sqk[mt][nt][1];
                Ss[(r + 8) * QLD + c]     = sqk[mt][nt][2];
                Ss[(r + 8) * QLD + c + 1] = sqk[mt][nt][3];
            }
        }
        __syncthreads();

        // ---- online softmax row pass: 2 threads per row, 32 values each ----
        {
            int row = tid >> 1, half = tid & 1;
            float* p = &Ss[row * QLD + half * 32];
            float4 v[8];
            float mx = -INFINITY;
            #pragma unroll
            for (int j = 0; j < 8; j++) {
                v[j] = *reinterpret_cast<const float4*>(&p[j * 4]);
                mx = fmaxf(mx, fmaxf(fmaxf(v[j].x, v[j].y), fmaxf(v[j].z, v[j].w)));
            }
            mx = fmaxf(mx, __shfl_xor_sync(0xffffffffu, mx, 1));
            float mold = rowm[row];
            float mnew = fmaxf(mold, mx);
            float sum = 0.f;
            #pragma unroll
            for (int j = 0; j < 8; j++) {
                float e0 = exp2f((v[j].x - mnew) * CEXP);
                float e1 = exp2f((v[j].y - mnew) * CEXP);
                float e2 = exp2f((v[j].z - mnew) * CEXP);
                float e3 = exp2f((v[j].w - mnew) * CEXP);
                sum += (e0 + e1) + (e2 + e3);
                float4 u = make_float4(tf32r(e0), tf32r(e1), tf32r(e2), tf32r(e3));
                *reinterpret_cast<float4*>(&p[j * 4]) = u;
            }
            sum += __shfl_xor_sync(0xffffffffu, sum, 1);
            if (half == 0) {
                float f = exp2f((mold - mnew) * CEXP);
                rowm[row] = mnew;
                rowl[row] = rowl[row] * f + sum;
                rowf[row] = f;
            }
        }
        __syncthreads();

        // ---- rescale O, then O += P @ V (this warp: 32 rows x 32 dims) ----
        #pragma unroll
        for (int mt = 0; mt < 2; mt++) {
            int r = warp_m * 32 + mt * 16 + qr;
            float f0 = rowf[r], f8 = rowf[r + 8];
            #pragma unroll
            for (int nt = 0; nt < 4; nt++) {
                o[mt][nt][0] *= f0; o[mt][nt][1] *= f0;
                o[mt][nt][2] *= f8; o[mt][nt][3] *= f8;
            }
        }
        #pragma unroll
        for (int ks = 0; ks < 8; ks++) {
            int kk = ks * 8;
            float af[2][4];
            #pragma unroll
            for (int mt = 0; mt < 2; mt++) {
                int r = warp_m * 32 + mt * 16 + qr;
                af[mt][0] = Ss[r * QLD + kk + qc];
                af[mt][1] = Ss[(r + 8) * QLD + kk + qc];
                af[mt][2] = Ss[r * QLD + kk + 4 + qc];
                af[mt][3] = Ss[(r + 8) * QLD + kk + 4 + qc];
            }
            float bf[4][2];
            #pragma unroll
            for (int nt = 0; nt < 4; nt++) {
                int cN = warp_n * 32 + nt * 8 + qr;
                bf[nt][0] = Vs[cN * QLD + kk + qc];
                bf[nt][1] = Vs[cN * QLD + kk + 4 + qc];
            }
            #pragma unroll
            for (int mt = 0; mt < 2; mt++)
                #pragma unroll
                for (int nt = 0; nt < 4; nt++)
                    mma_tf32(o[mt][nt], af[mt], bf[nt]);
        }
    }

    // ---- finalize: divide by l and store to att[B,L,E] ----
    #pragma unroll
    for (int mt = 0; mt < 2; mt++) {
        int r = warp_m * 32 + mt * 16 + qr;
        float inv0 = 1.f / rowl[r];
        float inv8 = 1.f / rowl[r + 8];
        #pragma unroll
        for (int nt = 0; nt < 4; nt++) {
            int col = hh * Dz + warp_n * 32 + nt * 8 + qc * 2;
            size_t gr0 = (size_t)bb * Lz + q0 + r;
            *reinterpret_cast<float2*>(&att[gr0 * Ez + col]) =
                make_float2(o[mt][nt][0] * inv0, o[mt][nt][1] * inv0);
            *reinterpret_cast<float2*>(&att[(gr0 + 8) * Ez + col]) =
                make_float2(o[mt][nt][2] * inv8, o[mt][nt][3] * inv8);
        }
    }
}

// ---------------- tiled transpose: dst[c][r] = src[r][c] (dims % 32 == 0) ----------------
__global__ void __launch_bounds__(256) transpose_k(
    const float* __restrict__ src, float* __restrict__ dst,
    int lds, int ldd, int NH,
    long long sSb, long long sSh, long long sDb, long long sDh)
{
    __shared__ float t[32][33];
    int z = blockIdx.z, bb = z / NH, hh = z % NH;
    src += bb * sSb + hh * sSh;
    dst += bb * sDb + hh * sDh;
    int r0 = blockIdx.y * 32, c0 = blockIdx.x * 32;
    int x = threadIdx.x & 31, y4 = (threadIdx.x >> 5) * 4;
    #pragma unroll
    for (int i = 0; i < 4; i++)
        t[y4 + i][x] = src[(long long)(r0 + y4 + i) * lds + c0 + x];
    __syncthreads();
    #pragma unroll
    for (int i = 0; i < 4; i++)
        dst[(long long)(c0 + y4 + i) * ldd + r0 + x] = t[x][y4 + i];
}

// ---------------- LayerNorm: one block per row of E=1024 ----------------
__global__ __launch_bounds__(256) void ln_k(
    const float* __restrict__ x, const float* __restrict__ g,
    const float* __restrict__ b, float* __restrict__ y)
{
    __shared__ float sh_s[8];
    __shared__ float sh_q[8];
    long long row = blockIdx.x;
    const float* xr = x + row * Ez;
    int t = threadIdx.x;

    float4 v = reinterpret_cast<const float4*>(xr)[t];
    float s  = v.x + v.y + v.z + v.w;
    float sq = v.x * v.x + v.y * v.y + v.z * v.z + v.w * v.w;
    #pragma unroll
    for (int o = 16; o > 0; o >>= 1) {
        s  += __shfl_down_sync(0xffffffffu, s,  o);
        sq += __shfl_down_sync(0xffffffffu, sq, o);
    }
    int warp = t >> 5, lane = t & 31;
    if (lane == 0) { sh_s[warp] = s; sh_q[warp] = sq; }
    __syncthreads();
    if (warp == 0) {
        s  = (lane < 8) ? sh_s[lane] : 0.f;
        sq = (lane < 8) ? sh_q[lane] : 0.f;
        #pragma unroll
        for (int o = 4; o > 0; o >>= 1) {
            s  += __shfl_down_sync(0xffffffffu, s,  o);
            sq += __shfl_down_sync(0xffffffffu, sq, o);
        }
        if (lane == 0) { sh_s[0] = s; sh_q[0] = sq; }
    }
    __syncthreads();
    float mu  = sh_s[0] * (1.f / Ez);
    float var = sh_q[0] * (1.f / Ez) - mu * mu;
    float inv = rsqrtf(var + 1e-5f);

    float4 gg = reinterpret_cast<const float4*>(g)[t];
    float4 bb = reinterpret_cast<const float4*>(b)[t];
    float4 o;
    o.x = (v.x - mu) * inv * gg.x + bb.x;
    o.y = (v.y - mu) * inv * gg.y + bb.y;
    o.z = (v.z - mu) * inv * gg.z + bb.z;
    o.w = (v.w - mu) * inv * gg.w + bb.w;
    reinterpret_cast<float4*>(y + row * Ez)[t] = o;
}

// ---------------- driver ----------------
extern "C" void kernel_launch(void* const* d_in, const int* in_sizes, int n_in,
                              void* d_out, int out_size)
{
    (void)in_sizes; (void)n_in; (void)out_size;
    const float* x      = (const float*)d_in[0];
    const float* ln1_g  = (const float*)d_in[1];
    const float* ln1_b  = (const float*)d_in[2];
    const float* W_qkv  = (const float*)d_in[3];
    const float* W_proj = (const float*)d_in[4];
    const float* b_proj = (const float*)d_in[5];
    const float* ln2_g  = (const float*)d_in[6];
    const float* ln2_b  = (const float*)d_in[7];
    const float* W1     = (const float*)d_in[8];
    const float* b1     = (const float*)d_in[9];
    const float* W2     = (const float*)d_in[10];
    const float* b2     = (const float*)d_in[11];
    float* out = (float*)d_out;

    float *h, *qkv, *att, *x1, *ffn, *wqkvT, *wprojT, *w1T, *w2T, *vT;
    cudaGetSymbolAddress((void**)&h,      g_h);
    cudaGetSymbolAddress((void**)&qkv,    g_qkv);
    cudaGetSymbolAddress((void**)&att,    g_att);
    cudaGetSymbolAddress((void**)&x1,     g_x1);
    cudaGetSymbolAddress((void**)&ffn,    g_ffn);
    cudaGetSymbolAddress((void**)&wqkvT,  g_wqkvT);
    cudaGetSymbolAddress((void**)&wprojT, g_wprojT);
    cudaGetSymbolAddress((void**)&w1T,    g_w1T);
    cudaGetSymbolAddress((void**)&w2T,    g_w2T);
    cudaGetSymbolAddress((void**)&vT,     g_vT);

    const int SMG128 = 2 * (128 + 128) * SLD * 4;   // 73728
    const int FLASH_SMEM = (128 * QLD + 64 * QLD + 64 * QLD + 128 * QLD + 3 * 128) * 4;
    cudaFuncSetAttribute(mma_gemm<128, EPI_NONE>,      cudaFuncAttributeMaxDynamicSharedMemorySize, SMG128);
    cudaFuncSetAttribute(mma_gemm<128, EPI_BIAS_RES>,  cudaFuncAttributeMaxDynamicSharedMemorySize, SMG128);
    cudaFuncSetAttribute(mma_gemm<128, EPI_BIAS_GELU>, cudaFuncAttributeMaxDynamicSharedMemorySize, SMG128);
    cudaFuncSetAttribute(flash_k, cudaFuncAttributeMaxDynamicSharedMemorySize, FLASH_SMEM);

    // 1. h = LN1(x)
    ln_k<<<BLz, 256>>>(x, ln1_g, ln1_b, h);

    // 2. one-shot weight transposes -> [N][K] K-major operands
    transpose_k<<<dim3(E3z / 32, Ez / 32, 1), 256>>>(W_qkv,  wqkvT,  E3z, Ez,  1, 0, 0, 0, 0);
    transpose_k<<<dim3(Ez  / 32, Ez / 32, 1), 256>>>(W_proj, wprojT, Ez,  Ez,  1, 0, 0, 0, 0);
    transpose_k<<<dim3(FFz / 32, Ez / 32, 1), 256>>>(W1,     w1T,    FFz, Ez,  1, 0, 0, 0, 0);
    transpose_k<<<dim3(Ez  / 32, FFz / 32, 1), 256>>>(W2,    w2T,    Ez,  FFz, 1, 0, 0, 0, 0);

    // 3. qkv = h @ W_qkv
    mma_gemm<128, EPI_NONE><<<dim3(E3z / 128, BLz / 128, 1), 256, SMG128>>>(
        h, wqkvT, qkv, nullptr, nullptr,
        Ez, Ez, Ez, E3z, 1, 0, 0, 0, 0, 0, 0);

    // 4. vT[b,h] = V[b,h]^T  ([D][L] per head)
    transpose_k<<<dim3(Dz / 32, Lz / 32, Bz * Hz), 256>>>(
        qkv + 2 * Ez, vT, E3z, Lz, Hz,
        (long long)Lz * E3z, Dz,
        (long long)Hz * Dz * Lz, (long long)Dz * Lz);

    // 5. att = flash(Q, K, V)  — fused QK^T + softmax + PV
    flash_k<<<dim3(Lz / 128, Bz * Hz), 256, FLASH_SMEM>>>(qkv, vT, att);

    // 6. x1 = x + att @ W_proj + b_proj
    mma_gemm<128, EPI_BIAS_RES><<<dim3(Ez / 128, BLz / 128, 1), 256, SMG128>>>(
        att, wprojT, x1, b_proj, x,
        Ez, Ez, Ez, Ez, 1, 0, 0, 0, 0, 0, 0);

    // 7. h = LN2(x1)
    ln_k<<<BLz, 256>>>(x1, ln2_g, ln2_b, h);

    // 8. ffn = gelu(h @ W1 + b1)
    mma_gemm<128, EPI_BIAS_GELU><<<dim3(FFz / 128, BLz / 128, 1), 256, SMG128>>>(
        h, w1T, ffn, b1, nullptr,
        Ez, Ez, Ez, FFz, 1, 0, 0, 0, 0, 0, 0);

    // 9. out = x1 + ffn @ W2 + b2
    mma_gemm<128, EPI_BIAS_RES><<<dim3(Ez / 128, BLz / 128, 1), 256, SMG128>>>(
        ffn, w2T, out, b2, x1,
        FFz, FFz, FFz, Ez, 1, 0, 0, 0, 0, 0, 0);
}

// round 11
// speedup vs baseline: 1.5572x; 1.5572x over previous
#include <cuda_runtime.h>
#include <math.h>
#include <stdint.h>

// Problem constants
#define Bz   2
#define Lz   2048
#define Ez   1024
#define Hz   16
#define Dz   64
#define BLz  (Bz*Lz)          // 4096 rows
#define E3z  (3*Ez)           // 3072
#define FFz  (4*Ez)           // 4096

// ---------------- static device scratch (no allocations allowed) ----------------
__device__ float g_h    [(size_t)BLz*Ez];
__device__ float g_qkv  [(size_t)BLz*E3z];
__device__ float g_att  [(size_t)BLz*Ez];
__device__ float g_x1   [(size_t)BLz*Ez];
__device__ float g_ffn  [(size_t)BLz*FFz];
__device__ float g_wqkvT[(size_t)E3z*Ez];
__device__ float g_wprojT[(size_t)Ez*Ez];
__device__ float g_w1T  [(size_t)FFz*Ez];
__device__ float g_w2T  [(size_t)Ez*FFz];
__device__ float g_vT   [(size_t)Bz*Hz*Dz*Lz];

// ---------------- helpers ----------------
static __device__ __forceinline__ float tf32r(float x) {
    uint32_t r;
    asm("cvt.rna.tf32.f32 %0, %1;" : "=r"(r) : "f"(x));
    return __uint_as_float(r);
}
static __device__ __forceinline__ void mma_tf32(
    float* c, const float* a, const float* b)
{
    asm volatile(
        "mma.sync.aligned.m16n8k8.row.col.f32.tf32.tf32.f32 "
        "{%0,%1,%2,%3}, {%4,%5,%6,%7}, {%8,%9}, {%0,%1,%2,%3};"
        : "+f"(c[0]), "+f"(c[1]), "+f"(c[2]), "+f"(c[3])
        : "r"(__float_as_uint(a[0])), "r"(__float_as_uint(a[1])),
          "r"(__float_as_uint(a[2])), "r"(__float_as_uint(a[3])),
          "r"(__float_as_uint(b[0])), "r"(__float_as_uint(b[1])));
}
#define CP16(dst_u32, src_ptr) \
    asm volatile("cp.async.cg.shared.global [%0], [%1], 16;" \
                 :: "r"(dst_u32), "l"(src_ptr))
#define CP_COMMIT()  asm volatile("cp.async.commit_group;" ::: "memory")
#define CP_WAIT1()   asm volatile("cp.async.wait_group 1;" ::: "memory")
#define CP_WAIT0()   asm volatile("cp.async.wait_group 0;" ::: "memory")

// ---------------- tf32 mma.sync GEMM: 128 x 128 tile, BK=32, 256 threads ----------------
// All operands are PRE-ROUNDED to tf32 by producer kernels: the mainloop has
// zero CVT instructions — cp.async raw fp32 bits, fragments feed MMA directly.
// A: [M,K] K-major (lda), B: [N,K] K-major (ldb), C: [M,N] (ldc).
enum { EPI_NONE = 0, EPI_BIAS_RES = 1, EPI_BIAS_GELU = 2 };

#define SLD 36   // smem row stride in floats (conflict-free fragment reads)

template<int BN, int EPI>
__global__ void __launch_bounds__(256, 2)
mma_gemm(const float* __restrict__ A, const float* __restrict__ B, float* __restrict__ C,
         const float* __restrict__ bias, const float* __restrict__ res,
         int K, int lda, int ldb, int ldc)
{
    constexpr int WN  = BN / 4;
    constexpr int NT  = WN / 8;
    constexpr int PBn = BN / 32;

    extern __shared__ float sm[];
    float* Asm = sm;                       // 2 x 128 x SLD
    float* Bsm = sm + 2 * 128 * SLD;       // 2 x BN x SLD

    int tid  = threadIdx.x;
    int lane = tid & 31;
    int wid  = tid >> 5;
    int warp_m = wid & 1;
    int warp_n = wid >> 1;

    int m0 = blockIdx.y * 128;
    int n0 = blockIdx.x * BN;

    uint32_t As_u = (uint32_t)__cvta_generic_to_shared(Asm);
    uint32_t Bs_u = (uint32_t)__cvta_generic_to_shared(Bsm);

    float acc[4][NT][4];
    #pragma unroll
    for (int i = 0; i < 4; i++)
        #pragma unroll
        for (int j = 0; j < NT; j++)
            #pragma unroll
            for (int k = 0; k < 4; k++) acc[i][j][k] = 0.f;

    const int slabs = K >> 5;

    auto issue = [&](int s, int b) {
        int k0 = s << 5;
        #pragma unroll
        for (int i = 0; i < 4; i++) {
            int e = tid + i * 256, row = e >> 3, c4 = e & 7;
            CP16(As_u + (uint32_t)(b * 128 * SLD + row * SLD + c4 * 4) * 4,
                 &A[(long long)(m0 + row) * lda + k0 + c4 * 4]);
        }
        #pragma unroll
        for (int i = 0; i < PBn; i++) {
            int e = tid + i * 256, row = e >> 3, c4 = e & 7;
            CP16(Bs_u + (uint32_t)(b * BN * SLD + row * SLD + c4 * 4) * 4,
                 &B[(long long)(n0 + row) * ldb + k0 + c4 * 4]);
        }
    };

    issue(0, 0);
    CP_COMMIT();

    int qr = lane >> 2, qc = lane & 3;
    for (int s = 0; s < slabs; s++) {
        if (s + 1 < slabs) {
            issue(s + 1, (s + 1) & 1);
            CP_COMMIT();
            CP_WAIT1();
        } else {
            CP_WAIT0();
        }
        __syncthreads();

        const float* Ab = Asm + (s & 1) * 128 * SLD;
        const float* Bb = Bsm + (s & 1) * BN * SLD;

        #pragma unroll
        for (int ks = 0; ks < 4; ks++) {
            int kk = ks * 8;
            float af[4][4];
            #pragma unroll
            for (int mt = 0; mt < 4; mt++) {
                int r = warp_m * 64 + mt * 16 + qr;
                af[mt][0] = Ab[r * SLD + kk + qc];
                af[mt][1] = Ab[(r + 8) * SLD + kk + qc];
                af[mt][2] = Ab[r * SLD + kk + 4 + qc];
                af[mt][3] = Ab[(r + 8) * SLD + kk + 4 + qc];
            }
            float bf[NT][2];
            #pragma unroll
            for (int nt = 0; nt < NT; nt++) {
                int cN = warp_n * WN + nt * 8 + qr;
                bf[nt][0] = Bb[cN * SLD + kk + qc];
                bf[nt][1] = Bb[cN * SLD + kk + 4 + qc];
            }
            #pragma unroll
            for (int mt = 0; mt < 4; mt++)
                #pragma unroll
                for (int nt = 0; nt < NT; nt++)
                    mma_tf32(acc[mt][nt], af[mt], bf[nt]);
        }
        __syncthreads();
    }

    #pragma unroll
    for (int mt = 0; mt < 4; mt++) {
        #pragma unroll
        for (int nt = 0; nt < NT; nt++) {
            int gc = n0 + warp_n * WN + nt * 8 + qc * 2;
            #pragma unroll
            for (int half = 0; half < 2; half++) {
                long long gr = m0 + warp_m * 64 + mt * 16 + qr + half * 8;
                float v0 = acc[mt][nt][half * 2 + 0];
                float v1 = acc[mt][nt][half * 2 + 1];
                if (EPI == EPI_BIAS_RES) {
                    v0 += bias[gc]     + res[gr * ldc + gc];
                    v1 += bias[gc + 1] + res[gr * ldc + gc + 1];
                }
                if (EPI == EPI_BIAS_GELU) {
                    v0 += bias[gc];
                    v1 += bias[gc + 1];
                    v0 = 0.5f * v0 * (1.f + erff(v0 * 0.70710678118654752f));
                    v1 = 0.5f * v1 * (1.f + erff(v1 * 0.70710678118654752f));
                    v0 = tf32r(v0);        // pre-round for the consuming GEMM
                    v1 = tf32r(v1);
                }
                *reinterpret_cast<float2*>(&C[gr * ldc + gc]) = make_float2(v0, v1);
            }
        }
    }
}

// ---------------- fused flash attention (proven R9 version, 128-key tiles) ----------------
// Grid: (Lz/128, Bz*Hz). 256 threads. One CTA = one (head, 128-query tile).
#define QLD 68    // Q/K smem stride  (68 % 32 == 4)
#define VLD 132   // V/S smem stride  (132 % 32 == 4)

__global__ void __launch_bounds__(256, 1)
flash_k(const float* __restrict__ qkv, const float* __restrict__ vT,
        float* __restrict__ att)
{
    extern __shared__ float sm[];
    float* Qs   = sm;                    // 128 x QLD
    float* Ks   = Qs + 128 * QLD;        // 128 x QLD
    float* Vs   = Ks + 128 * QLD;        // 64  x VLD  (dim-major: Vs[d][key])
    float* Ss   = Vs + 64 * VLD;         // 128 x VLD
    float* rowm = Ss + 128 * VLD;        // 128
    float* rowl = rowm + 128;            // 128
    float* rowf = rowl + 128;            // 128

    int tid  = threadIdx.x;
    int lane = tid & 31;
    int wid  = tid >> 5;
    int qr = lane >> 2, qc = lane & 3;
    int warp_m = wid >> 1;               // 0..3 : 32 query rows each
    int warp_n = wid & 1;                // 0..1 : QK cols 64 each, PV cols 32 each

    int bb = blockIdx.y >> 4;            // Hz = 16
    int hh = blockIdx.y & 15;
    int q0 = blockIdx.x * 128;
    const float CEXP = 1.4426950408889634f / 32.f;   // log2(e)/sqrt(E)

    const float* Qg = qkv + (size_t)bb * Lz * E3z + hh * Dz;
    const float* Kg = qkv + (size_t)bb * Lz * E3z + Ez + hh * Dz;
    const float* Vg = vT + ((size_t)(bb * Hz + hh)) * Dz * Lz;

    // load Q tile (128 x 64), tf32-rounded
    #pragma unroll
    for (int i = 0; i < 8; i++) {
        int e = tid + i * 256, row = e >> 4, c4 = e & 15;
        float4 v = *reinterpret_cast<const float4*>(&Qg[(size_t)(q0 + row) * E3z + c4 * 4]);
        float4 u = make_float4(tf32r(v.x), tf32r(v.y), tf32r(v.z), tf32r(v.w));
        *reinterpret_cast<float4*>(&Qs[row * QLD + c4 * 4]) = u;
    }
    if (tid < 128) { rowm[tid] = -INFINITY; rowl[tid] = 0.f; }

    float o[2][4][4];
    #pragma unroll
    for (int mt = 0; mt < 2; mt++)
        #pragma unroll
        for (int nt = 0; nt < 4; nt++)
            #pragma unroll
            for (int k = 0; k < 4; k++) o[mt][nt][k] = 0.f;

    for (int kt = 0; kt < 16; kt++) {
        __syncthreads();    // prev PV reads of Ks/Vs/Ss done; Q visible on iter 0

        // fill K tile (128 keys x 64 dims)
        #pragma unroll
        for (int i = 0; i < 8; i++) {
            int e = tid + i * 256, row = e >> 4, c4 = e & 15;
            float4 v = *reinterpret_cast<const float4*>(
                &Kg[(size_t)(kt * 128 + row) * E3z + c4 * 4]);
            float4 u = make_float4(tf32r(v.x), tf32r(v.y), tf32r(v.z), tf32r(v.w));
            *reinterpret_cast<float4*>(&Ks[row * QLD + c4 * 4]) = u;
        }
        // fill V tile (64 dims x 128 keys), dim-major from vT (pre-rounded)
        #pragma unroll
        for (int i = 0; i < 8; i++) {
            int e = tid + i * 256, row = e >> 5, c4 = e & 31;
            float4 v = *reinterpret_cast<const float4*>(
                &Vg[(size_t)row * Lz + kt * 128 + c4 * 4]);
            *reinterpret_cast<float4*>(&Vs[row * VLD + c4 * 4]) = v;
        }
        __syncthreads();

        // ---- S = Q @ K^T (this warp: 32 rows x 64 cols) ----
        float sqk[2][8][4];
        #pragma unroll
        for (int mt = 0; mt < 2; mt++)
            #pragma unroll
            for (int nt = 0; nt < 8; nt++)
                #pragma unroll
                for (int k = 0; k < 4; k++) sqk[mt][nt][k] = 0.f;

        #pragma unroll
        for (int ks = 0; ks < 8; ks++) {
            int kk = ks * 8;
            float af[2][4];
            #pragma unroll
            for (int mt = 0; mt < 2; mt++) {
                int r = warp_m * 32 + mt * 16 + qr;
                af[mt][0] = Qs[r * QLD + kk + qc];
                af[mt][1] = Qs[(r + 8) * QLD + kk + qc];
                af[mt][2] = Qs[r * QLD + kk + 4 + qc];
                af[mt][3] = Qs[(r + 8) * QLD + kk + 4 + qc];
            }
            float bf[8][2];
            #pragma unroll
            for (int nt = 0; nt < 8; nt++) {
                int cN = warp_n * 64 + nt * 8 + qr;
                bf[nt][0] = Ks[cN * QLD + kk + qc];
                bf[nt][1] = Ks[cN * QLD + kk + 4 + qc];
            }
            #pragma unroll
            for (int mt = 0; mt < 2; mt++)
                #pragma unroll
                for (int nt = 0; nt < 8; nt++)
                    mma_tf32(sqk[mt][nt], af[mt], bf[nt]);
        }
        // spill S fragments to smem
        #pragma unroll
        for (int mt = 0; mt < 2; mt++) {
            int r = warp_m * 32 + mt * 16 + qr;
            #pragma unroll
            for (int nt = 0; nt < 8; nt++) {
                int c = warp_n * 64 + nt * 8 + qc * 2;
                Ss[r * VLD + c]           = sqk[mt][nt][0];
                Ss[r * VLD + c + 1]       = sqk[mt][nt][1];
                Ss[(r + 8) * VLD + c]     = sqk[mt][nt][2];
                Ss[(r + 8) * VLD + c + 1] = sqk[mt][nt][3];
            }
        }
        __syncthreads();

        // ---- online softmax row pass: 2 threads per row ----
        {
            int row = tid >> 1, half = tid & 1;
            float* p = &Ss[row * VLD + half * 64];
            float4 v[16];
            float mx = -INFINITY;
            #pragma unroll
            for (int j = 0; j < 16; j++) {
                v[j] = *reinterpret_cast<const float4*>(&p[j * 4]);
                mx = fmaxf(mx, fmaxf(fmaxf(v[j].x, v[j].y), fmaxf(v[j].z, v[j].w)));
            }
            mx = fmaxf(mx, __shfl_xor_sync(0xffffffffu, mx, 1));
            float mold = rowm[row];
            float mnew = fmaxf(mold, mx);
            float sum = 0.f;
            #pragma unroll
            for (int j = 0; j < 16; j++) {
                float e0 = exp2f((v[j].x - mnew) * CEXP);
                float e1 = exp2f((v[j].y - mnew) * CEXP);
                float e2 = exp2f((v[j].z - mnew) * CEXP);
                float e3 = exp2f((v[j].w - mnew) * CEXP);
                sum += (e0 + e1) + (e2 + e3);
                float4 u = make_float4(tf32r(e0), tf32r(e1), tf32r(e2), tf32r(e3));
                *reinterpret_cast<float4*>(&p[j * 4]) = u;
            }
            sum += __shfl_xor_sync(0xffffffffu, sum, 1);
            if (half == 0) {
                float f = exp2f((mold - mnew) * CEXP);
                rowm[row] = mnew;
                rowl[row] = rowl[row] * f + sum;
                rowf[row] = f;
            }
        }
        __syncthreads();

        // ---- rescale O, then O += P @ V (this warp: 32 rows x 32 dims) ----
        #pragma unroll
        for (int mt = 0; mt < 2; mt++) {
            int r = warp_m * 32 + mt * 16 + qr;
            float f0 = rowf[r], f8 = rowf[r + 8];
            #pragma unroll
            for (int nt = 0; nt < 4; nt++) {
                o[mt][nt][0] *= f0; o[mt][nt][1] *= f0;
                o[mt][nt][2] *= f8; o[mt][nt][3] *= f8;
            }
        }
        #pragma unroll
        for (int ks = 0; ks < 16; ks++) {
            int kk = ks * 8;
            float af[2][4];
            #pragma unroll
            for (int mt = 0; mt < 2; mt++) {
                int r = warp_m * 32 + mt * 16 + qr;
                af[mt][0] = Ss[r * VLD + kk + qc];
                af[mt][1] = Ss[(r + 8) * VLD + kk + qc];
                af[mt][2] = Ss[r * VLD + kk + 4 + qc];
                af[mt][3] = Ss[(r + 8) * VLD + kk + 4 + qc];
            }
            float bf[4][2];
            #pragma unroll
            for (int nt = 0; nt < 4; nt++) {
                int cN = warp_n * 32 + nt * 8 + qr;
                bf[nt][0] = Vs[cN * VLD + kk + qc];
                bf[nt][1] = Vs[cN * VLD + kk + 4 + qc];
            }
            #pragma unroll
            for (int mt = 0; mt < 2; mt++)
                #pragma unroll
                for (int nt = 0; nt < 4; nt++)
                    mma_tf32(o[mt][nt], af[mt], bf[nt]);
        }
    }

    // ---- finalize: divide by l, tf32-round (pre-round for proj GEMM), store ----
    #pragma unroll
    for (int mt = 0; mt < 2; mt++) {
        int r = warp_m * 32 + mt * 16 + qr;
        float inv0 = 1.f / rowl[r];
        float inv8 = 1.f / rowl[r + 8];
        #pragma unroll
        for (int nt = 0; nt < 4; nt++) {
            int col = hh * Dz + warp_n * 32 + nt * 8 + qc * 2;
            size_t gr0 = (size_t)bb * Lz + q0 + r;
            *reinterpret_cast<float2*>(&att[gr0 * Ez + col]) =
                make_float2(tf32r(o[mt][nt][0] * inv0), tf32r(o[mt][nt][1] * inv0));
            *reinterpret_cast<float2*>(&att[(gr0 + 8) * Ez + col]) =
                make_float2(tf32r(o[mt][nt][2] * inv8), tf32r(o[mt][nt][3] * inv8));
        }
    }
}

// ---------------- tiled transpose (+ tf32 pre-round): dst[c][r] = tf32(src[r][c]) ----------------
__global__ void __launch_bounds__(256) transpose_k(
    const float* __restrict__ src, float* __restrict__ dst,
    int lds, int ldd, int NH,
    long long sSb, long long sSh, long long sDb, long long sDh)
{
    __shared__ float t[32][33];
    int z = blockIdx.z, bb = z / NH, hh = z % NH;
    src += bb * sSb + hh * sSh;
    dst += bb * sDb + hh * sDh;
    int r0 = blockIdx.y * 32, c0 = blockIdx.x * 32;
    int x = threadIdx.x & 31, y4 = (threadIdx.x >> 5) * 4;
    #pragma unroll
    for (int i = 0; i < 4; i++)
        t[y4 + i][x] = tf32r(src[(long long)(r0 + y4 + i) * lds + c0 + x]);
    __syncthreads();
    #pragma unroll
    for (int i = 0; i < 4; i++)
        dst[(long long)(c0 + y4 + i) * ldd + r0 + x] = t[x][y4 + i];
}

// ---------------- LayerNorm (+ tf32 pre-round of output) ----------------
__global__ __launch_bounds__(256) void ln_k(
    const float* __restrict__ x, const float* __restrict__ g,
    const float* __restrict__ b, float* __restrict__ y)
{
    __shared__ float sh_s[8];
    __shared__ float sh_q[8];
    long long row = blockIdx.x;
    const float* xr = x + row * Ez;
    int t = threadIdx.x;

    float4 v = reinterpret_cast<const float4*>(xr)[t];
    float s  = v.x + v.y + v.z + v.w;
    float sq = v.x * v.x + v.y * v.y + v.z * v.z + v.w * v.w;
    #pragma unroll
    for (int o = 16; o > 0; o >>= 1) {
        s  += __shfl_down_sync(0xffffffffu, s,  o);
        sq += __shfl_down_sync(0xffffffffu, sq, o);
    }
    int warp = t >> 5, lane = t & 31;
    if (lane == 0) { sh_s[warp] = s; sh_q[warp] = sq; }
    __syncthreads();
    if (warp == 0) {
        s  = (lane < 8) ? sh_s[lane] : 0.f;
        sq = (lane < 8) ? sh_q[lane] : 0.f;
        #pragma unroll
        for (int o = 4; o > 0; o >>= 1) {
            s  += __shfl_down_sync(0xffffffffu, s,  o);
            sq += __shfl_down_sync(0xffffffffu, sq, o);
        }
        if (lane == 0) { sh_s[0] = s; sh_q[0] = sq; }
    }
    __syncthreads();
    float mu  = sh_s[0] * (1.f / Ez);
    float var = sh_q[0] * (1.f / Ez) - mu * mu;
    float inv = rsqrtf(var + 1e-5f);

    float4 gg = reinterpret_cast<const float4*>(g)[t];
    float4 bb = reinterpret_cast<const float4*>(b)[t];
    float4 o;
    o.x = tf32r((v.x - mu) * inv * gg.x + bb.x);
    o.y = tf32r((v.y - mu) * inv * gg.y + bb.y);
    o.z = tf32r((v.z - mu) * inv * gg.z + bb.z);
    o.w = tf32r((v.w - mu) * inv * gg.w + bb.w);
    reinterpret_cast<float4*>(y + row * Ez)[t] = o;
}

// ---------------- driver ----------------
extern "C" void kernel_launch(void* const* d_in, const int* in_sizes, int n_in,
                              void* d_out, int out_size)
{
    (void)in_sizes; (void)n_in; (void)out_size;
    const float* x      = (const float*)d_in[0];
    const float* ln1_g  = (const float*)d_in[1];
    const float* ln1_b  = (const float*)d_in[2];
    const float* W_qkv  = (const float*)d_in[3];
    const float* W_proj = (const float*)d_in[4];
    const float* b_proj = (const float*)d_in[5];
    const float* ln2_g  = (const float*)d_in[6];
    const float* ln2_b  = (const float*)d_in[7];
    const float* W1     = (const float*)d_in[8];
    const float* b1     = (const float*)d_in[9];
    const float* W2     = (const float*)d_in[10];
    const float* b2     = (const float*)d_in[11];
    float* out = (float*)d_out;

    float *h, *qkv, *att, *x1, *ffn, *wqkvT, *wprojT, *w1T, *w2T, *vT;
    cudaGetSymbolAddress((void**)&h,      g_h);
    cudaGetSymbolAddress((void**)&qkv,    g_qkv);
    cudaGetSymbolAddress((void**)&att,    g_att);
    cudaGetSymbolAddress((void**)&x1,     g_x1);
    cudaGetSymbolAddress((void**)&ffn,    g_ffn);
    cudaGetSymbolAddress((void**)&wqkvT,  g_wqkvT);
    cudaGetSymbolAddress((void**)&wprojT, g_wprojT);
    cudaGetSymbolAddress((void**)&w1T,    g_w1T);
    cudaGetSymbolAddress((void**)&w2T,    g_w2T);
    cudaGetSymbolAddress((void**)&vT,     g_vT);

    const int SMG128 = 2 * (128 + 128) * SLD * 4;   // 73728 bytes
    const int FLASH_SMEM = (2 * 128 * QLD + 64 * VLD + 128 * VLD + 3 * 128) * 4;
    cudaFuncSetAttribute(mma_gemm<128, EPI_NONE>,      cudaFuncAttributeMaxDynamicSharedMemorySize, SMG128);
    cudaFuncSetAttribute(mma_gemm<128, EPI_BIAS_RES>,  cudaFuncAttributeMaxDynamicSharedMemorySize, SMG128);
    cudaFuncSetAttribute(mma_gemm<128, EPI_BIAS_GELU>, cudaFuncAttributeMaxDynamicSharedMemorySize, SMG128);
    cudaFuncSetAttribute(flash_k, cudaFuncAttributeMaxDynamicSharedMemorySize, FLASH_SMEM);

    // 1. h = tf32(LN1(x))
    ln_k<<<BLz, 256>>>(x, ln1_g, ln1_b, h);

    // 2. one-shot weight transposes -> tf32-rounded [N][K] K-major operands
    transpose_k<<<dim3(E3z / 32, Ez / 32, 1), 256>>>(W_qkv,  wqkvT,  E3z, Ez,  1, 0, 0, 0, 0);
    transpose_k<<<dim3(Ez  / 32, Ez / 32, 1), 256>>>(W_proj, wprojT, Ez,  Ez,  1, 0, 0, 0, 0);
    transpose_k<<<dim3(FFz / 32, Ez / 32, 1), 256>>>(W1,     w1T,    FFz, Ez,  1, 0, 0, 0, 0);
    transpose_k<<<dim3(Ez  / 32, FFz / 32, 1), 256>>>(W2,    w2T,    Ez,  FFz, 1, 0, 0, 0, 0);

    // 3. qkv = h @ W_qkv
    mma_gemm<128, EPI_NONE><<<dim3(E3z / 128, BLz / 128, 1), 256, SMG128>>>(
        h, wqkvT, qkv, nullptr, nullptr, Ez, Ez, Ez, E3z);

    // 4. vT[b,h] = tf32(V[b,h]^T)  ([D][L] per head)
    transpose_k<<<dim3(Dz / 32, Lz / 32, Bz * Hz), 256>>>(
        qkv + 2 * Ez, vT, E3z, Lz, Hz,
        (long long)Lz * E3z, Dz,
        (long long)Hz * Dz * Lz, (long long)Dz * Lz);

    // 5. att = flash(Q, K, V)  — fused QK^T + softmax + PV, output tf32-rounded
    flash_k<<<dim3(Lz / 128, Bz * Hz), 256, FLASH_SMEM>>>(qkv, vT, att);

    // 6. x1 = x + att @ W_proj + b_proj   (fp32 exact output)
    mma_gemm<128, EPI_BIAS_RES><<<dim3(Ez / 128, BLz / 128, 1), 256, SMG128>>>(
        att, wprojT, x1, b_proj, x, Ez, Ez, Ez, Ez);

    // 7. h = tf32(LN2(x1))
    ln_k<<<BLz, 256>>>(x1, ln2_g, ln2_b, h);

    // 8. ffn = tf32(gelu(h @ W1 + b1))
    mma_gemm<128, EPI_BIAS_GELU><<<dim3(FFz / 128, BLz / 128, 1), 256, SMG128>>>(
        h, w1T, ffn, b1, nullptr, Ez, Ez, Ez, FFz);

    // 9. out = x1 + ffn @ W2 + b2   (fp32 final output)
    mma_gemm<128, EPI_BIAS_RES><<<dim3(Ez / 128, BLz / 128, 1), 256, SMG128>>>(
        ffn, w2T, out, b2, x1, FFz, FFz, FFz, Ez);
}

// round 12
// speedup vs baseline: 2.2144x; 1.4220x over previous
#include <cuda_runtime.h>
#include <cuda_fp16.h>
#include <math.h>
#include <stdint.h>

// Problem constants
#define Bz   2
#define Lz   2048
#define Ez   1024
#define Hz   16
#define Dz   64
#define BLz  (Bz*Lz)          // 4096 rows
#define E3z  (3*Ez)           // 3072
#define FFz  (4*Ez)           // 4096

// ---------------- static device scratch (no allocations allowed) ----------------
__device__ __half g_h    [(size_t)BLz*Ez];          // fp16 LN output (GEMM A)
__device__ float  g_qkv  [(size_t)BLz*E3z];         // fp32 qkv (flash input)
__device__ __half g_att  [(size_t)BLz*Ez];          // fp16 attention out (GEMM A)
__device__ float  g_x1   [(size_t)BLz*Ez];          // fp32 residual
__device__ __half g_ffn  [(size_t)BLz*FFz];         // fp16 gelu out (GEMM A)
__device__ __half g_wqkvT[(size_t)E3z*Ez];          // fp16 weights^T (GEMM B)
__device__ __half g_wprojT[(size_t)Ez*Ez];
__device__ __half g_w1T  [(size_t)FFz*Ez];
__device__ __half g_w2T  [(size_t)Ez*FFz];
__device__ float  g_vT   [(size_t)Bz*Hz*Dz*Lz];     // fp32 V^T (flash input)

// ---------------- helpers ----------------
static __device__ __forceinline__ float tf32r(float x) {
    uint32_t r;
    asm("cvt.rna.tf32.f32 %0, %1;" : "=r"(r) : "f"(x));
    return __uint_as_float(r);
}
static __device__ __forceinline__ void mma_tf32(
    float* c, const float* a, const float* b)
{
    asm volatile(
        "mma.sync.aligned.m16n8k8.row.col.f32.tf32.tf32.f32 "
        "{%0,%1,%2,%3}, {%4,%5,%6,%7}, {%8,%9}, {%0,%1,%2,%3};"
        : "+f"(c[0]), "+f"(c[1]), "+f"(c[2]), "+f"(c[3])
        : "r"(__float_as_uint(a[0])), "r"(__float_as_uint(a[1])),
          "r"(__float_as_uint(a[2])), "r"(__float_as_uint(a[3])),
          "r"(__float_as_uint(b[0])), "r"(__float_as_uint(b[1])));
}
static __device__ __forceinline__ void mma_fp16(
    float* c, const uint32_t* a, const uint32_t* b)
{
    asm volatile(
        "mma.sync.aligned.m16n8k16.row.col.f32.f16.f16.f32 "
        "{%0,%1,%2,%3}, {%4,%5,%6,%7}, {%8,%9}, {%0,%1,%2,%3};"
        : "+f"(c[0]), "+f"(c[1]), "+f"(c[2]), "+f"(c[3])
        : "r"(a[0]), "r"(a[1]), "r"(a[2]), "r"(a[3]),
          "r"(b[0]), "r"(b[1]));
}
#define CP16(dst_u32, src_ptr) \
    asm volatile("cp.async.cg.shared.global [%0], [%1], 16;" \
                 :: "r"(dst_u32), "l"(src_ptr))
#define CP_COMMIT()  asm volatile("cp.async.commit_group;" ::: "memory")
#define CP_WAIT1()   asm volatile("cp.async.wait_group 1;" ::: "memory")
#define CP_WAIT0()   asm volatile("cp.async.wait_group 0;" ::: "memory")

// ---------------- fp16 mma.sync GEMM: 128x128 tile, BK=64, 256 threads ----------------
// A: [M,K] K-major fp16 (lda), B: [N,K] K-major fp16 (ldb), C: [M,N] fp32 or fp16.
// m16n8k16 fragments; smem stride 72 halves (36 words, proven conflict-free residue).
enum { EPI_NONE = 0, EPI_BIAS_RES = 1, EPI_BIAS_GELU = 2 };

#define SLDH 72   // smem row stride in halves

template<int EPI, bool OUT_HALF>
__global__ void __launch_bounds__(256, 2)
mma_gemm(const __half* __restrict__ A, const __half* __restrict__ B, void* __restrict__ Cv,
         const float* __restrict__ bias, const float* __restrict__ res,
         int K, int lda, int ldb, int ldc)
{
    extern __shared__ __half smh[];
    __half* Asm = smh;                         // 2 x 128 x SLDH
    __half* Bsm = smh + 2 * 128 * SLDH;        // 2 x 128 x SLDH

    int tid  = threadIdx.x;
    int lane = tid & 31;
    int wid  = tid >> 5;
    int warp_m = wid & 1;      // 2 warps along m (64 rows each)
    int warp_n = wid >> 1;     // 4 warps along n (32 cols each)

    int m0 = blockIdx.y * 128;
    int n0 = blockIdx.x * 128;

    uint32_t As_u = (uint32_t)__cvta_generic_to_shared(Asm);
    uint32_t Bs_u = (uint32_t)__cvta_generic_to_shared(Bsm);

    float acc[4][4][4];
    #pragma unroll
    for (int i = 0; i < 4; i++)
        #pragma unroll
        for (int j = 0; j < 4; j++)
            #pragma unroll
            for (int k = 0; k < 4; k++) acc[i][j][k] = 0.f;

    const int slabs = K >> 6;   // BK = 64

    auto issue = [&](int s, int b) {
        int k0 = s << 6;
        #pragma unroll
        for (int i = 0; i < 4; i++) {          // A: 128 rows x 64 halves
            int e = tid + i * 256, row = e >> 3, c8 = e & 7;
            CP16(As_u + (uint32_t)(b * 128 * SLDH + row * SLDH + c8 * 8) * 2,
                 &A[(long long)(m0 + row) * lda + k0 + c8 * 8]);
        }
        #pragma unroll
        for (int i = 0; i < 4; i++) {          // B: 128 rows x 64 halves
            int e = tid + i * 256, row = e >> 3, c8 = e & 7;
            CP16(Bs_u + (uint32_t)(b * 128 * SLDH + row * SLDH + c8 * 8) * 2,
                 &B[(long long)(n0 + row) * ldb + k0 + c8 * 8]);
        }
    };

    issue(0, 0);
    CP_COMMIT();

    int qr = lane >> 2, qc = lane & 3;
    for (int s = 0; s < slabs; s++) {
        if (s + 1 < slabs) {
            issue(s + 1, (s + 1) & 1);
            CP_COMMIT();
            CP_WAIT1();
        } else {
            CP_WAIT0();
        }
        __syncthreads();

        const __half* Ab = Asm + (s & 1) * 128 * SLDH;
        const __half* Bb = Bsm + (s & 1) * 128 * SLDH;

        #pragma unroll
        for (int ks = 0; ks < 4; ks++) {       // 4 x k16
            int kk = ks * 16;
            uint32_t af[4][4];
            #pragma unroll
            for (int mt = 0; mt < 4; mt++) {
                int r = warp_m * 64 + mt * 16 + qr;
                af[mt][0] = *reinterpret_cast<const uint32_t*>(&Ab[r * SLDH + kk + 2 * qc]);
                af[mt][1] = *reinterpret_cast<const uint32_t*>(&Ab[(r + 8) * SLDH + kk + 2 * qc]);
                af[mt][2] = *reinterpret_cast<const uint32_t*>(&Ab[r * SLDH + kk + 8 + 2 * qc]);
                af[mt][3] = *reinterpret_cast<const uint32_t*>(&Ab[(r + 8) * SLDH + kk + 8 + 2 * qc]);
            }
            uint32_t bf[4][2];
            #pragma unroll
            for (int nt = 0; nt < 4; nt++) {
                int cN = warp_n * 32 + nt * 8 + qr;
                bf[nt][0] = *reinterpret_cast<const uint32_t*>(&Bb[cN * SLDH + kk + 2 * qc]);
                bf[nt][1] = *reinterpret_cast<const uint32_t*>(&Bb[cN * SLDH + kk + 8 + 2 * qc]);
            }
            #pragma unroll
            for (int mt = 0; mt < 4; mt++)
                #pragma unroll
                for (int nt = 0; nt < 4; nt++)
                    mma_fp16(acc[mt][nt], af[mt], bf[nt]);
        }
        __syncthreads();
    }

    float*  Cf = reinterpret_cast<float*>(Cv);
    __half* Ch = reinterpret_cast<__half*>(Cv);

    #pragma unroll
    for (int mt = 0; mt < 4; mt++) {
        #pragma unroll
        for (int nt = 0; nt < 4; nt++) {
            int gc = n0 + warp_n * 32 + nt * 8 + qc * 2;
            #pragma unroll
            for (int half_i = 0; half_i < 2; half_i++) {
                long long gr = m0 + warp_m * 64 + mt * 16 + qr + half_i * 8;
                float v0 = acc[mt][nt][half_i * 2 + 0];
                float v1 = acc[mt][nt][half_i * 2 + 1];
                if (EPI == EPI_BIAS_RES) {
                    v0 += bias[gc]     + res[gr * ldc + gc];
                    v1 += bias[gc + 1] + res[gr * ldc + gc + 1];
                }
                if (EPI == EPI_BIAS_GELU) {
                    v0 += bias[gc];
                    v1 += bias[gc + 1];
                    v0 = 0.5f * v0 * (1.f + erff(v0 * 0.70710678118654752f));
                    v1 = 0.5f * v1 * (1.f + erff(v1 * 0.70710678118654752f));
                }
                if (OUT_HALF)
                    *reinterpret_cast<__half2*>(&Ch[gr * ldc + gc]) = __floats2half2_rn(v0, v1);
                else
                    *reinterpret_cast<float2*>(&Cf[gr * ldc + gc]) = make_float2(v0, v1);
            }
        }
    }
}

// ---------------- fused flash attention (proven tf32 version, 128-key tiles) ----------------
// Grid: (Lz/128, Bz*Hz). 256 threads. One CTA = one (head, 128-query tile).
#define QLD 68    // Q/K smem stride  (68 % 32 == 4)
#define VLD 132   // V/S smem stride  (132 % 32 == 4)

__global__ void __launch_bounds__(256, 1)
flash_k(const float* __restrict__ qkv, const float* __restrict__ vT,
        __half* __restrict__ att)
{
    extern __shared__ float sm[];
    float* Qs   = sm;                    // 128 x QLD
    float* Ks   = Qs + 128 * QLD;        // 128 x QLD
    float* Vs   = Ks + 128 * QLD;        // 64  x VLD  (dim-major: Vs[d][key])
    float* Ss   = Vs + 64 * VLD;         // 128 x VLD
    float* rowm = Ss + 128 * VLD;        // 128
    float* rowl = rowm + 128;            // 128
    float* rowf = rowl + 128;            // 128

    int tid  = threadIdx.x;
    int lane = tid & 31;
    int wid  = tid >> 5;
    int qr = lane >> 2, qc = lane & 3;
    int warp_m = wid >> 1;               // 0..3 : 32 query rows each
    int warp_n = wid & 1;                // 0..1 : QK cols 64 each, PV cols 32 each

    int bb = blockIdx.y >> 4;            // Hz = 16
    int hh = blockIdx.y & 15;
    int q0 = blockIdx.x * 128;
    const float CEXP = 1.4426950408889634f / 32.f;   // log2(e)/sqrt(E)

    const float* Qg = qkv + (size_t)bb * Lz * E3z + hh * Dz;
    const float* Kg = qkv + (size_t)bb * Lz * E3z + Ez + hh * Dz;
    const float* Vg = vT + ((size_t)(bb * Hz + hh)) * Dz * Lz;

    // load Q tile (128 x 64), tf32-rounded
    #pragma unroll
    for (int i = 0; i < 8; i++) {
        int e = tid + i * 256, row = e >> 4, c4 = e & 15;
        float4 v = *reinterpret_cast<const float4*>(&Qg[(size_t)(q0 + row) * E3z + c4 * 4]);
        float4 u = make_float4(tf32r(v.x), tf32r(v.y), tf32r(v.z), tf32r(v.w));
        *reinterpret_cast<float4*>(&Qs[row * QLD + c4 * 4]) = u;
    }
    if (tid < 128) { rowm[tid] = -INFINITY; rowl[tid] = 0.f; }

    float o[2][4][4];
    #pragma unroll
    for (int mt = 0; mt < 2; mt++)
        #pragma unroll
        for (int nt = 0; nt < 4; nt++)
            #pragma unroll
            for (int k = 0; k < 4; k++) o[mt][nt][k] = 0.f;

    for (int kt = 0; kt < 16; kt++) {
        __syncthreads();    // prev PV reads of Ks/Vs/Ss done; Q visible on iter 0

        // fill K tile (128 keys x 64 dims)
        #pragma unroll
        for (int i = 0; i < 8; i++) {
            int e = tid + i * 256, row = e >> 4, c4 = e & 15;
            float4 v = *reinterpret_cast<const float4*>(
                &Kg[(size_t)(kt * 128 + row) * E3z + c4 * 4]);
            float4 u = make_float4(tf32r(v.x), tf32r(v.y), tf32r(v.z), tf32r(v.w));
            *reinterpret_cast<float4*>(&Ks[row * QLD + c4 * 4]) = u;
        }
        // fill V tile (64 dims x 128 keys), dim-major from vT (pre-rounded)
        #pragma unroll
        for (int i = 0; i < 8; i++) {
            int e = tid + i * 256, row = e >> 5, c4 = e & 31;
            float4 v = *reinterpret_cast<const float4*>(
                &Vg[(size_t)row * Lz + kt * 128 + c4 * 4]);
            *reinterpret_cast<float4*>(&Vs[row * VLD + c4 * 4]) = v;
        }
        __syncthreads();

        // ---- S = Q @ K^T (this warp: 32 rows x 64 cols) ----
        float sqk[2][8][4];
        #pragma unroll
        for (int mt = 0; mt < 2; mt++)
            #pragma unroll
            for (int nt = 0; nt < 8; nt++)
                #pragma unroll
                for (int k = 0; k < 4; k++) sqk[mt][nt][k] = 0.f;

        #pragma unroll
        for (int ks = 0; ks < 8; ks++) {
            int kk = ks * 8;
            float af[2][4];
            #pragma unroll
            for (int mt = 0; mt < 2; mt++) {
                int r = warp_m * 32 + mt * 16 + qr;
                af[mt][0] = Qs[r * QLD + kk + qc];
                af[mt][1] = Qs[(r + 8) * QLD + kk + qc];
                af[mt][2] = Qs[r * QLD + kk + 4 + qc];
                af[mt][3] = Qs[(r + 8) * QLD + kk + 4 + qc];
            }
            float bf[8][2];
            #pragma unroll
            for (int nt = 0; nt < 8; nt++) {
                int cN = warp_n * 64 + nt * 8 + qr;
                bf[nt][0] = Ks[cN * QLD + kk + qc];
                bf[nt][1] = Ks[cN * QLD + kk + 4 + qc];
            }
            #pragma unroll
            for (int mt = 0; mt < 2; mt++)
                #pragma unroll
                for (int nt = 0; nt < 8; nt++)
                    mma_tf32(sqk[mt][nt], af[mt], bf[nt]);
        }
        // spill S fragments to smem
        #pragma unroll
        for (int mt = 0; mt < 2; mt++) {
            int r = warp_m * 32 + mt * 16 + qr;
            #pragma unroll
            for (int nt = 0; nt < 8; nt++) {
                int c = warp_n * 64 + nt * 8 + qc * 2;
                Ss[r * VLD + c]           = sqk[mt][nt][0];
                Ss[r * VLD + c + 1]       = sqk[mt][nt][1];
                Ss[(r + 8) * VLD + c]     = sqk[mt][nt][2];
                Ss[(r + 8) * VLD + c + 1] = sqk[mt][nt][3];
            }
        }
        __syncthreads();

        // ---- online softmax row pass: 2 threads per row ----
        {
            int row = tid >> 1, half_i = tid & 1;
            float* p = &Ss[row * VLD + half_i * 64];
            float4 v[16];
            float mx = -INFINITY;
            #pragma unroll
            for (int j = 0; j < 16; j++) {
                v[j] = *reinterpret_cast<const float4*>(&p[j * 4]);
                mx = fmaxf(mx, fmaxf(fmaxf(v[j].x, v[j].y), fmaxf(v[j].z, v[j].w)));
            }
            mx = fmaxf(mx, __shfl_xor_sync(0xffffffffu, mx, 1));
            float mold = rowm[row];
            float mnew = fmaxf(mold, mx);
            float sum = 0.f;
            #pragma unroll
            for (int j = 0; j < 16; j++) {
                float e0 = exp2f((v[j].x - mnew) * CEXP);
                float e1 = exp2f((v[j].y - mnew) * CEXP);
                float e2 = exp2f((v[j].z - mnew) * CEXP);
                float e3 = exp2f((v[j].w - mnew) * CEXP);
                sum += (e0 + e1) + (e2 + e3);
                float4 u = make_float4(tf32r(e0), tf32r(e1), tf32r(e2), tf32r(e3));
                *reinterpret_cast<float4*>(&p[j * 4]) = u;
            }
            sum += __shfl_xor_sync(0xffffffffu, sum, 1);
            if (half_i == 0) {
                float f = exp2f((mold - mnew) * CEXP);
                rowm[row] = mnew;
                rowl[row] = rowl[row] * f + sum;
                rowf[row] = f;
            }
        }
        __syncthreads();

        // ---- rescale O, then O += P @ V (this warp: 32 rows x 32 dims) ----
        #pragma unroll
        for (int mt = 0; mt < 2; mt++) {
            int r = warp_m * 32 + mt * 16 + qr;
            float f0 = rowf[r], f8 = rowf[r + 8];
            #pragma unroll
            for (int nt = 0; nt < 4; nt++) {
                o[mt][nt][0] *= f0; o[mt][nt][1] *= f0;
                o[mt][nt][2] *= f8; o[mt][nt][3] *= f8;
            }
        }
        #pragma unroll
        for (int ks = 0; ks < 16; ks++) {
            int kk = ks * 8;
            float af[2][4];
            #pragma unroll
            for (int mt = 0; mt < 2; mt++) {
                int r = warp_m * 32 + mt * 16 + qr;
                af[mt][0] = Ss[r * VLD + kk + qc];
                af[mt][1] = Ss[(r + 8) * VLD + kk + qc];
                af[mt][2] = Ss[r * VLD + kk + 4 + qc];
                af[mt][3] = Ss[(r + 8) * VLD + kk + 4 + qc];
            }
            float bf[4][2];
            #pragma unroll
            for (int nt = 0; nt < 4; nt++) {
                int cN = warp_n * 32 + nt * 8 + qr;
                bf[nt][0] = Vs[cN * VLD + kk + qc];
                bf[nt][1] = Vs[cN * VLD + kk + 4 + qc];
            }
            #pragma unroll
            for (int mt = 0; mt < 2; mt++)
                #pragma unroll
                for (int nt = 0; nt < 4; nt++)
                    mma_tf32(o[mt][nt], af[mt], bf[nt]);
        }
    }

    // ---- finalize: divide by l, store fp16 (operand of proj GEMM) ----
    #pragma unroll
    for (int mt = 0; mt < 2; mt++) {
        int r = warp_m * 32 + mt * 16 + qr;
        float inv0 = 1.f / rowl[r];
        float inv8 = 1.f / rowl[r + 8];
        #pragma unroll
        for (int nt = 0; nt < 4; nt++) {
            int col = hh * Dz + warp_n * 32 + nt * 8 + qc * 2;
            size_t gr0 = (size_t)bb * Lz + q0 + r;
            *reinterpret_cast<__half2*>(&att[gr0 * Ez + col]) =
                __floats2half2_rn(o[mt][nt][0] * inv0, o[mt][nt][1] * inv0);
            *reinterpret_cast<__half2*>(&att[(gr0 + 8) * Ez + col]) =
                __floats2half2_rn(o[mt][nt][2] * inv8, o[mt][nt][3] * inv8);
        }
    }
}

// ---------------- tiled transpose with output conversion ----------------
// OUT=__half: fp16 round (weights).  OUT=float: tf32 round (vT for flash).
template<typename OUT>
__global__ void __launch_bounds__(256) transpose_k(
    const float* __restrict__ src, OUT* __restrict__ dst,
    int lds, int ldd, int NH,
    long long sSb, long long sSh, long long sDb, long long sDh)
{
    __shared__ float t[32][33];
    int z = blockIdx.z, bb = z / NH, hh = z % NH;
    src += bb * sSb + hh * sSh;
    dst += bb * sDb + hh * sDh;
    int r0 = blockIdx.y * 32, c0 = blockIdx.x * 32;
    int x = threadIdx.x & 31, y4 = (threadIdx.x >> 5) * 4;
    #pragma unroll
    for (int i = 0; i < 4; i++)
        t[y4 + i][x] = src[(long long)(r0 + y4 + i) * lds + c0 + x];
    __syncthreads();
    #pragma unroll
    for (int i = 0; i < 4; i++) {
        float v = t[x][y4 + i];
        if (sizeof(OUT) == 2)
            dst[(long long)(c0 + y4 + i) * ldd + r0 + x] = (OUT)__float2half_rn(v);
        else
            dst[(long long)(c0 + y4 + i) * ldd + r0 + x] = (OUT)tf32r(v);
    }
}

// ---------------- LayerNorm, fp16 output ----------------
__global__ __launch_bounds__(256) void ln_k(
    const float* __restrict__ x, const float* __restrict__ g,
    const float* __restrict__ b, __half* __restrict__ y)
{
    __shared__ float sh_s[8];
    __shared__ float sh_q[8];
    long long row = blockIdx.x;
    const float* xr = x + row * Ez;
    int t = threadIdx.x;

    float4 v = reinterpret_cast<const float4*>(xr)[t];
    float s  = v.x + v.y + v.z + v.w;
    float sq = v.x * v.x + v.y * v.y + v.z * v.z + v.w * v.w;
    #pragma unroll
    for (int o = 16; o > 0; o >>= 1) {
        s  += __shfl_down_sync(0xffffffffu, s,  o);
        sq += __shfl_down_sync(0xffffffffu, sq, o);
    }
    int warp = t >> 5, lane = t & 31;
    if (lane == 0) { sh_s[warp] = s; sh_q[warp] = sq; }
    __syncthreads();
    if (warp == 0) {
        s  = (lane < 8) ? sh_s[lane] : 0.f;
        sq = (lane < 8) ? sh_q[lane] : 0.f;
        #pragma unroll
        for (int o = 4; o > 0; o >>= 1) {
            s  += __shfl_down_sync(0xffffffffu, s,  o);
            sq += __shfl_down_sync(0xffffffffu, sq, o);
        }
        if (lane == 0) { sh_s[0] = s; sh_q[0] = sq; }
    }
    __syncthreads();
    float mu  = sh_s[0] * (1.f / Ez);
    float var = sh_q[0] * (1.f / Ez) - mu * mu;
    float inv = rsqrtf(var + 1e-5f);

    float4 gg = reinterpret_cast<const float4*>(g)[t];
    float4 bb = reinterpret_cast<const float4*>(b)[t];
    __half2 o0 = __floats2half2_rn((v.x - mu) * inv * gg.x + bb.x,
                                   (v.y - mu) * inv * gg.y + bb.y);
    __half2 o1 = __floats2half2_rn((v.z - mu) * inv * gg.z + bb.z,
                                   (v.w - mu) * inv * gg.w + bb.w);
    uint2 pk = make_uint2(*reinterpret_cast<uint32_t*>(&o0),
                          *reinterpret_cast<uint32_t*>(&o1));
    reinterpret_cast<uint2*>(y + row * Ez)[t] = pk;
}

// ---------------- driver ----------------
extern "C" void kernel_launch(void* const* d_in, const int* in_sizes, int n_in,
                              void* d_out, int out_size)
{
    (void)in_sizes; (void)n_in; (void)out_size;
    const float* x      = (const float*)d_in[0];
    const float* ln1_g  = (const float*)d_in[1];
    const float* ln1_b  = (const float*)d_in[2];
    const float* W_qkv  = (const float*)d_in[3];
    const float* W_proj = (const float*)d_in[4];
    const float* b_proj = (const float*)d_in[5];
    const float* ln2_g  = (const float*)d_in[6];
    const float* ln2_b  = (const float*)d_in[7];
    const float* W1     = (const float*)d_in[8];
    const float* b1     = (const float*)d_in[9];
    const float* W2     = (const float*)d_in[10];
    const float* b2     = (const float*)d_in[11];
    float* out = (float*)d_out;

    __half *h, *att, *ffn, *wqkvT, *wprojT, *w1T, *w2T;
    float *qkv, *x1, *vT;
    cudaGetSymbolAddress((void**)&h,      g_h);
    cudaGetSymbolAddress((void**)&qkv,    g_qkv);
    cudaGetSymbolAddress((void**)&att,    g_att);
    cudaGetSymbolAddress((void**)&x1,     g_x1);
    cudaGetSymbolAddress((void**)&ffn,    g_ffn);
    cudaGetSymbolAddress((void**)&wqkvT,  g_wqkvT);
    cudaGetSymbolAddress((void**)&wprojT, g_wprojT);
    cudaGetSymbolAddress((void**)&w1T,    g_w1T);
    cudaGetSymbolAddress((void**)&w2T,    g_w2T);
    cudaGetSymbolAddress((void**)&vT,     g_vT);

    const int SMG = 2 * (128 + 128) * SLDH * 2;   // 73728 bytes
    const int FLASH_SMEM = (2 * 128 * QLD + 64 * VLD + 128 * VLD + 3 * 128) * 4;
    cudaFuncSetAttribute(mma_gemm<EPI_NONE,      false>, cudaFuncAttributeMaxDynamicSharedMemorySize, SMG);
    cudaFuncSetAttribute(mma_gemm<EPI_BIAS_RES,  false>, cudaFuncAttributeMaxDynamicSharedMemorySize, SMG);
    cudaFuncSetAttribute(mma_gemm<EPI_BIAS_GELU, true >, cudaFuncAttributeMaxDynamicSharedMemorySize, SMG);
    cudaFuncSetAttribute(flash_k, cudaFuncAttributeMaxDynamicSharedMemorySize, FLASH_SMEM);

    // 1. h = fp16(LN1(x))
    ln_k<<<BLz, 256>>>(x, ln1_g, ln1_b, h);

    // 2. weight transposes -> fp16 [N][K] K-major operands
    transpose_k<__half><<<dim3(E3z / 32, Ez / 32, 1), 256>>>(W_qkv,  wqkvT,  E3z, Ez,  1, 0, 0, 0, 0);
    transpose_k<__half><<<dim3(Ez  / 32, Ez / 32, 1), 256>>>(W_proj, wprojT, Ez,  Ez,  1, 0, 0, 0, 0);
    transpose_k<__half><<<dim3(FFz / 32, Ez / 32, 1), 256>>>(W1,     w1T,    FFz, Ez,  1, 0, 0, 0, 0);
    transpose_k<__half><<<dim3(Ez  / 32, FFz / 32, 1), 256>>>(W2,    w2T,    Ez,  FFz, 1, 0, 0, 0, 0);

    // 3. qkv = h @ W_qkv   (fp32 output for flash)
    mma_gemm<EPI_NONE, false><<<dim3(E3z / 128, BLz / 128, 1), 256, SMG>>>(
        h, wqkvT, qkv, nullptr, nullptr, Ez, Ez, Ez, E3z);

    // 4. vT[b,h] = tf32(V[b,h]^T)  ([D][L] per head, fp32 for flash)
    transpose_k<float><<<dim3(Dz / 32, Lz / 32, Bz * Hz), 256>>>(
        qkv + 2 * Ez, vT, E3z, Lz, Hz,
        (long long)Lz * E3z, Dz,
        (long long)Hz * Dz * Lz, (long long)Dz * Lz);

    // 5. att = flash(Q, K, V)  — fp16 output (proj GEMM operand)
    flash_k<<<dim3(Lz / 128, Bz * Hz), 256, FLASH_SMEM>>>(qkv, vT, att);

    // 6. x1 = x + att @ W_proj + b_proj   (fp32)
    mma_gemm<EPI_BIAS_RES, false><<<dim3(Ez / 128, BLz / 128, 1), 256, SMG>>>(
        att, wprojT, x1, b_proj, x, Ez, Ez, Ez, Ez);

    // 7. h = fp16(LN2(x1))
    ln_k<<<BLz, 256>>>(x1, ln2_g, ln2_b, h);

    // 8. ffn = fp16(gelu(h @ W1 + b1))
    mma_gemm<EPI_BIAS_GELU, true><<<dim3(FFz / 128, BLz / 128, 1), 256, SMG>>>(
        h, w1T, ffn, b1, nullptr, Ez, Ez, Ez, FFz);

    // 9. out = x1 + ffn @ W2 + b2   (fp32 final output)
    mma_gemm<EPI_BIAS_RES, false><<<dim3(Ez / 128, BLz / 128, 1), 256, SMG>>>(
        ffn, w2T, out, b2, x1, FFz, FFz, FFz, Ez);
}

// round 13
// speedup vs baseline: 3.0108x; 1.3596x over previous
#include <cuda_runtime.h>
#include <cuda_fp16.h>
#include <math.h>
#include <stdint.h>

// Problem constants
#define Bz   2
#define Lz   2048
#define Ez   1024
#define Hz   16
#define Dz   64
#define BLz  (Bz*Lz)          // 4096 rows
#define E3z  (3*Ez)           // 3072
#define FFz  (4*Ez)           // 4096

// ---------------- static device scratch (no allocations allowed) ----------------
__device__ __half g_h    [(size_t)BLz*Ez];          // fp16 LN output (GEMM A)
__device__ __half g_qkv  [(size_t)BLz*E3z];         // fp16 qkv (flash input)
__device__ __half g_att  [(size_t)BLz*Ez];          // fp16 attention out (GEMM A)
__device__ float  g_x1   [(size_t)BLz*Ez];          // fp32 residual
__device__ __half g_ffn  [(size_t)BLz*FFz];         // fp16 gelu out (GEMM A)
__device__ __half g_wqkvT[(size_t)E3z*Ez];          // fp16 weights^T (GEMM B)
__device__ __half g_wprojT[(size_t)Ez*Ez];
__device__ __half g_w1T  [(size_t)FFz*Ez];
__device__ __half g_w2T  [(size_t)Ez*FFz];
__device__ __half g_vT   [(size_t)Bz*Hz*Dz*Lz];     // fp16 V^T (flash input)

// ---------------- helpers ----------------
static __device__ __forceinline__ void mma_fp16(
    float* c, const uint32_t* a, const uint32_t* b)
{
    asm volatile(
        "mma.sync.aligned.m16n8k16.row.col.f32.f16.f16.f32 "
        "{%0,%1,%2,%3}, {%4,%5,%6,%7}, {%8,%9}, {%0,%1,%2,%3};"
        : "+f"(c[0]), "+f"(c[1]), "+f"(c[2]), "+f"(c[3])
        : "r"(a[0]), "r"(a[1]), "r"(a[2]), "r"(a[3]),
          "r"(b[0]), "r"(b[1]));
}
#define CP16(dst_u32, src_ptr) \
    asm volatile("cp.async.cg.shared.global [%0], [%1], 16;" \
                 :: "r"(dst_u32), "l"(src_ptr))
#define CP_COMMIT()  asm volatile("cp.async.commit_group;" ::: "memory")
#define CP_WAIT1()   asm volatile("cp.async.wait_group 1;" ::: "memory")
#define CP_WAIT0()   asm volatile("cp.async.wait_group 0;" ::: "memory")

// ---------------- fp16 mma.sync GEMM: 128x128 tile, BK=64, 256 threads ----------------
enum { EPI_NONE = 0, EPI_BIAS_RES = 1, EPI_BIAS_GELU = 2 };

#define SLDH 72   // smem row stride in halves (36 words, residue 4 mod 32)

template<int EPI, bool OUT_HALF>
__global__ void __launch_bounds__(256, 2)
mma_gemm(const __half* __restrict__ A, const __half* __restrict__ B, void* __restrict__ Cv,
         const float* __restrict__ bias, const float* __restrict__ res,
         int K, int lda, int ldb, int ldc)
{
    extern __shared__ __half smh[];
    __half* Asm = smh;                         // 2 x 128 x SLDH
    __half* Bsm = smh + 2 * 128 * SLDH;        // 2 x 128 x SLDH

    int tid  = threadIdx.x;
    int lane = tid & 31;
    int wid  = tid >> 5;
    int warp_m = wid & 1;
    int warp_n = wid >> 1;

    int m0 = blockIdx.y * 128;
    int n0 = blockIdx.x * 128;

    uint32_t As_u = (uint32_t)__cvta_generic_to_shared(Asm);
    uint32_t Bs_u = (uint32_t)__cvta_generic_to_shared(Bsm);

    float acc[4][4][4];
    #pragma unroll
    for (int i = 0; i < 4; i++)
        #pragma unroll
        for (int j = 0; j < 4; j++)
            #pragma unroll
            for (int k = 0; k < 4; k++) acc[i][j][k] = 0.f;

    const int slabs = K >> 6;   // BK = 64

    auto issue = [&](int s, int b) {
        int k0 = s << 6;
        #pragma unroll
        for (int i = 0; i < 4; i++) {
            int e = tid + i * 256, row = e >> 3, c8 = e & 7;
            CP16(As_u + (uint32_t)(b * 128 * SLDH + row * SLDH + c8 * 8) * 2,
                 &A[(long long)(m0 + row) * lda + k0 + c8 * 8]);
        }
        #pragma unroll
        for (int i = 0; i < 4; i++) {
            int e = tid + i * 256, row = e >> 3, c8 = e & 7;
            CP16(Bs_u + (uint32_t)(b * 128 * SLDH + row * SLDH + c8 * 8) * 2,
                 &B[(long long)(n0 + row) * ldb + k0 + c8 * 8]);
        }
    };

    issue(0, 0);
    CP_COMMIT();

    int qr = lane >> 2, qc = lane & 3;
    for (int s = 0; s < slabs; s++) {
        if (s + 1 < slabs) {
            issue(s + 1, (s + 1) & 1);
            CP_COMMIT();
            CP_WAIT1();
        } else {
            CP_WAIT0();
        }
        __syncthreads();

        const __half* Ab = Asm + (s & 1) * 128 * SLDH;
        const __half* Bb = Bsm + (s & 1) * 128 * SLDH;

        #pragma unroll
        for (int ks = 0; ks < 4; ks++) {
            int kk = ks * 16;
            uint32_t af[4][4];
            #pragma unroll
            for (int mt = 0; mt < 4; mt++) {
                int r = warp_m * 64 + mt * 16 + qr;
                af[mt][0] = *reinterpret_cast<const uint32_t*>(&Ab[r * SLDH + kk + 2 * qc]);
                af[mt][1] = *reinterpret_cast<const uint32_t*>(&Ab[(r + 8) * SLDH + kk + 2 * qc]);
                af[mt][2] = *reinterpret_cast<const uint32_t*>(&Ab[r * SLDH + kk + 8 + 2 * qc]);
                af[mt][3] = *reinterpret_cast<const uint32_t*>(&Ab[(r + 8) * SLDH + kk + 8 + 2 * qc]);
            }
            uint32_t bf[4][2];
            #pragma unroll
            for (int nt = 0; nt < 4; nt++) {
                int cN = warp_n * 32 + nt * 8 + qr;
                bf[nt][0] = *reinterpret_cast<const uint32_t*>(&Bb[cN * SLDH + kk + 2 * qc]);
                bf[nt][1] = *reinterpret_cast<const uint32_t*>(&Bb[cN * SLDH + kk + 8 + 2 * qc]);
            }
            #pragma unroll
            for (int mt = 0; mt < 4; mt++)
                #pragma unroll
                for (int nt = 0; nt < 4; nt++)
                    mma_fp16(acc[mt][nt], af[mt], bf[nt]);
        }
        __syncthreads();
    }

    float*  Cf = reinterpret_cast<float*>(Cv);
    __half* Ch = reinterpret_cast<__half*>(Cv);

    #pragma unroll
    for (int mt = 0; mt < 4; mt++) {
        #pragma unroll
        for (int nt = 0; nt < 4; nt++) {
            int gc = n0 + warp_n * 32 + nt * 8 + qc * 2;
            #pragma unroll
            for (int half_i = 0; half_i < 2; half_i++) {
                long long gr = m0 + warp_m * 64 + mt * 16 + qr + half_i * 8;
                float v0 = acc[mt][nt][half_i * 2 + 0];
                float v1 = acc[mt][nt][half_i * 2 + 1];
                if (EPI == EPI_BIAS_RES) {
                    v0 += bias[gc]     + res[gr * ldc + gc];
                    v1 += bias[gc + 1] + res[gr * ldc + gc + 1];
                }
                if (EPI == EPI_BIAS_GELU) {
                    v0 += bias[gc];
                    v1 += bias[gc + 1];
                    v0 = 0.5f * v0 * (1.f + erff(v0 * 0.70710678118654752f));
                    v1 = 0.5f * v1 * (1.f + erff(v1 * 0.70710678118654752f));
                }
                if (OUT_HALF)
                    *reinterpret_cast<__half2*>(&Ch[gr * ldc + gc]) = __floats2half2_rn(v0, v1);
                else
                    *reinterpret_cast<float2*>(&Cf[gr * ldc + gc]) = make_float2(v0, v1);
            }
        }
    }
}

// ---------------- fp16 flash attention, register softmax, 64-key tiles ----------------
// Grid: (Lz/128, Bz*Hz). 256 threads. Each warp owns 16 query rows x ALL 64 key cols,
// so softmax stats live in registers (quad shuffles), P fragments feed PV directly.
#define QLDH 72   // smem stride in halves for Q/K/V tiles

__global__ void __launch_bounds__(256, 2)
flash_k(const __half* __restrict__ qkv, const __half* __restrict__ vT,
        __half* __restrict__ att)
{
    extern __shared__ __half smh[];
    __half* Qs = smh;               // 128 x QLDH  (query rows x dims)
    __half* Ks = Qs + 128 * QLDH;   // 64  x QLDH  (keys x dims)
    __half* Vs = Ks + 64 * QLDH;    // 64  x QLDH  (dims x keys)

    int tid  = threadIdx.x;
    int lane = tid & 31;
    int wid  = tid >> 5;
    int qr = lane >> 2, qc = lane & 3;

    int bb = blockIdx.y >> 4;       // Hz = 16
    int hh = blockIdx.y & 15;
    int q0 = blockIdx.x * 128;
    const float CEXP = 1.4426950408889634f / 32.f;   // log2(e)/sqrt(E)

    const __half* Qg = qkv + (size_t)bb * Lz * E3z + hh * Dz;
    const __half* Kg = qkv + (size_t)bb * Lz * E3z + Ez + hh * Dz;
    const __half* Vg = vT + ((size_t)(bb * Hz + hh)) * Dz * Lz;

    // Q tile (128 x 64 halves), loaded once
    #pragma unroll
    for (int i = 0; i < 4; i++) {
        int e = tid + i * 256, row = e >> 3, c8 = e & 7;
        *reinterpret_cast<float4*>(&Qs[row * QLDH + c8 * 8]) =
            *reinterpret_cast<const float4*>(&Qg[(size_t)(q0 + row) * E3z + c8 * 8]);
    }

    float o[8][4];
    #pragma unroll
    for (int nt = 0; nt < 8; nt++)
        #pragma unroll
        for (int k = 0; k < 4; k++) o[nt][k] = 0.f;
    float m0 = -INFINITY, m1 = -INFINITY, l0 = 0.f, l1 = 0.f;

    for (int kt = 0; kt < 32; kt++) {
        __syncthreads();   // prior QK/PV reads of Ks/Vs done (and Q visible, iter 0)

        // K tile: 64 keys x 64 dims
        #pragma unroll
        for (int i = 0; i < 2; i++) {
            int e = tid + i * 256, row = e >> 3, c8 = e & 7;
            *reinterpret_cast<float4*>(&Ks[row * QLDH + c8 * 8]) =
                *reinterpret_cast<const float4*>(&Kg[(size_t)(kt * 64 + row) * E3z + c8 * 8]);
        }
        // V tile: 64 dims x 64 keys (dim-major from vT)
        #pragma unroll
        for (int i = 0; i < 2; i++) {
            int e = tid + i * 256, row = e >> 3, c8 = e & 7;
            *reinterpret_cast<float4*>(&Vs[row * QLDH + c8 * 8]) =
                *reinterpret_cast<const float4*>(&Vg[(size_t)row * Lz + kt * 64 + c8 * 8]);
        }
        __syncthreads();

        // ---- S = Q @ K^T : this warp's 16 rows x 64 cols ----
        float s[8][4];
        #pragma unroll
        for (int nt = 0; nt < 8; nt++)
            #pragma unroll
            for (int k = 0; k < 4; k++) s[nt][k] = 0.f;

        #pragma unroll
        for (int ks = 0; ks < 4; ks++) {
            int kk = ks * 16;
            int r = wid * 16 + qr;
            uint32_t a[4];
            a[0] = *reinterpret_cast<const uint32_t*>(&Qs[r * QLDH + kk + 2 * qc]);
            a[1] = *reinterpret_cast<const uint32_t*>(&Qs[(r + 8) * QLDH + kk + 2 * qc]);
            a[2] = *reinterpret_cast<const uint32_t*>(&Qs[r * QLDH + kk + 8 + 2 * qc]);
            a[3] = *reinterpret_cast<const uint32_t*>(&Qs[(r + 8) * QLDH + kk + 8 + 2 * qc]);
            #pragma unroll
            for (int nt = 0; nt < 8; nt++) {
                int cN = nt * 8 + qr;
                uint32_t b[2];
                b[0] = *reinterpret_cast<const uint32_t*>(&Ks[cN * QLDH + kk + 2 * qc]);
                b[1] = *reinterpret_cast<const uint32_t*>(&Ks[cN * QLDH + kk + 8 + 2 * qc]);
                mma_fp16(s[nt], a, b);
            }
        }

        // ---- register online softmax (rows qr and qr+8; reduce over quad) ----
        float mx0 = -INFINITY, mx1 = -INFINITY;
        #pragma unroll
        for (int nt = 0; nt < 8; nt++) {
            mx0 = fmaxf(mx0, fmaxf(s[nt][0], s[nt][1]));
            mx1 = fmaxf(mx1, fmaxf(s[nt][2], s[nt][3]));
        }
        mx0 = fmaxf(mx0, __shfl_xor_sync(0xffffffffu, mx0, 1));
        mx0 = fmaxf(mx0, __shfl_xor_sync(0xffffffffu, mx0, 2));
        mx1 = fmaxf(mx1, __shfl_xor_sync(0xffffffffu, mx1, 1));
        mx1 = fmaxf(mx1, __shfl_xor_sync(0xffffffffu, mx1, 2));

        float mn0 = fmaxf(m0, mx0), mn1 = fmaxf(m1, mx1);
        float f0 = exp2f((m0 - mn0) * CEXP);
        float f1 = exp2f((m1 - mn1) * CEXP);

        float sum0 = 0.f, sum1 = 0.f;
        uint32_t p0[8], p1[8];
        #pragma unroll
        for (int nt = 0; nt < 8; nt++) {
            float e0 = exp2f((s[nt][0] - mn0) * CEXP);
            float e1 = exp2f((s[nt][1] - mn0) * CEXP);
            float e2 = exp2f((s[nt][2] - mn1) * CEXP);
            float e3 = exp2f((s[nt][3] - mn1) * CEXP);
            sum0 += e0 + e1;
            sum1 += e2 + e3;
            __half2 h0 = __floats2half2_rn(e0, e1);
            __half2 h1 = __floats2half2_rn(e2, e3);
            p0[nt] = *reinterpret_cast<uint32_t*>(&h0);
            p1[nt] = *reinterpret_cast<uint32_t*>(&h1);
        }
        sum0 += __shfl_xor_sync(0xffffffffu, sum0, 1);
        sum0 += __shfl_xor_sync(0xffffffffu, sum0, 2);
        sum1 += __shfl_xor_sync(0xffffffffu, sum1, 1);
        sum1 += __shfl_xor_sync(0xffffffffu, sum1, 2);

        l0 = l0 * f0 + sum0;  m0 = mn0;
        l1 = l1 * f1 + sum1;  m1 = mn1;

        #pragma unroll
        for (int nt = 0; nt < 8; nt++) {
            o[nt][0] *= f0; o[nt][1] *= f0;
            o[nt][2] *= f1; o[nt][3] *= f1;
        }

        // ---- O += P @ V : P fragments come straight from registers ----
        #pragma unroll
        for (int kt2 = 0; kt2 < 4; kt2++) {
            int kk = kt2 * 16;
            uint32_t a[4] = { p0[2 * kt2], p1[2 * kt2], p0[2 * kt2 + 1], p1[2 * kt2 + 1] };
            #pragma unroll
            for (int nt = 0; nt < 8; nt++) {
                int cN = nt * 8 + qr;
                uint32_t b[2];
                b[0] = *reinterpret_cast<const uint32_t*>(&Vs[cN * QLDH + kk + 2 * qc]);
                b[1] = *reinterpret_cast<const uint32_t*>(&Vs[cN * QLDH + kk + 8 + 2 * qc]);
                mma_fp16(o[nt], a, b);
            }
        }
    }

    // ---- finalize: divide by l, store fp16 att[B,L,E] ----
    float i0 = 1.f / l0, i1 = 1.f / l1;
    size_t r0g = (size_t)bb * Lz + q0 + wid * 16 + qr;
    #pragma unroll
    for (int nt = 0; nt < 8; nt++) {
        int col = hh * Dz + nt * 8 + 2 * qc;
        *reinterpret_cast<__half2*>(&att[r0g * Ez + col]) =
            __floats2half2_rn(o[nt][0] * i0, o[nt][1] * i0);
        *reinterpret_cast<__half2*>(&att[(r0g + 8) * Ez + col]) =
            __floats2half2_rn(o[nt][2] * i1, o[nt][3] * i1);
    }
}

// ---------------- fp32 -> fp16 tiled transpose (weights) ----------------
__global__ void __launch_bounds__(256) transpose_k(
    const float* __restrict__ src, __half* __restrict__ dst, int lds, int ldd)
{
    __shared__ float t[32][33];
    int r0 = blockIdx.y * 32, c0 = blockIdx.x * 32;
    int x = threadIdx.x & 31, y4 = (threadIdx.x >> 5) * 4;
    #pragma unroll
    for (int i = 0; i < 4; i++)
        t[y4 + i][x] = src[(long long)(r0 + y4 + i) * lds + c0 + x];
    __syncthreads();
    #pragma unroll
    for (int i = 0; i < 4; i++)
        dst[(long long)(c0 + y4 + i) * ldd + r0 + x] = __float2half_rn(t[x][y4 + i]);
}

// ---------------- fp16 -> fp16 tiled transpose (V per head) ----------------
__global__ void __launch_bounds__(256) transpose_h(
    const __half* __restrict__ src, __half* __restrict__ dst,
    int lds, int ldd, int NH,
    long long sSb, long long sSh, long long sDb, long long sDh)
{
    __shared__ __half t[32][34];
    int z = blockIdx.z, bb = z / NH, hh = z % NH;
    src += bb * sSb + hh * sSh;
    dst += bb * sDb + hh * sDh;
    int r0 = blockIdx.y * 32, c0 = blockIdx.x * 32;
    int x = threadIdx.x & 31, y4 = (threadIdx.x >> 5) * 4;
    #pragma unroll
    for (int i = 0; i < 4; i++)
        t[y4 + i][x] = src[(long long)(r0 + y4 + i) * lds + c0 + x];
    __syncthreads();
    #pragma unroll
    for (int i = 0; i < 4; i++)
        dst[(long long)(c0 + y4 + i) * ldd + r0 + x] = t[x][y4 + i];
}

// ---------------- LayerNorm, fp16 output ----------------
__global__ __launch_bounds__(256) void ln_k(
    const float* __restrict__ x, const float* __restrict__ g,
    const float* __restrict__ b, __half* __restrict__ y)
{
    __shared__ float sh_s[8];
    __shared__ float sh_q[8];
    long long row = blockIdx.x;
    const float* xr = x + row * Ez;
    int t = threadIdx.x;

    float4 v = reinterpret_cast<const float4*>(xr)[t];
    float s  = v.x + v.y + v.z + v.w;
    float sq = v.x * v.x + v.y * v.y + v.z * v.z + v.w * v.w;
    #pragma unroll
    for (int o = 16; o > 0; o >>= 1) {
        s  += __shfl_down_sync(0xffffffffu, s,  o);
        sq += __shfl_down_sync(0xffffffffu, sq, o);
    }
    int warp = t >> 5, lane = t & 31;
    if (lane == 0) { sh_s[warp] = s; sh_q[warp] = sq; }
    __syncthreads();
    if (warp == 0) {
        s  = (lane < 8) ? sh_s[lane] : 0.f;
        sq = (lane < 8) ? sh_q[lane] : 0.f;
        #pragma unroll
        for (int o = 4; o > 0; o >>= 1) {
            s  += __shfl_down_sync(0xffffffffu, s,  o);
            sq += __shfl_down_sync(0xffffffffu, sq, o);
        }
        if (lane == 0) { sh_s[0] = s; sh_q[0] = sq; }
    }
    __syncthreads();
    float mu  = sh_s[0] * (1.f / Ez);
    float var = sh_q[0] * (1.f / Ez) - mu * mu;
    float inv = rsqrtf(var + 1e-5f);

    float4 gg = reinterpret_cast<const float4*>(g)[t];
    float4 bb = reinterpret_cast<const float4*>(b)[t];
    __half2 o0 = __floats2half2_rn((v.x - mu) * inv * gg.x + bb.x,
                                   (v.y - mu) * inv * gg.y + bb.y);
    __half2 o1 = __floats2half2_rn((v.z - mu) * inv * gg.z + bb.z,
                                   (v.w - mu) * inv * gg.w + bb.w);
    uint2 pk = make_uint2(*reinterpret_cast<uint32_t*>(&o0),
                          *reinterpret_cast<uint32_t*>(&o1));
    reinterpret_cast<uint2*>(y + row * Ez)[t] = pk;
}

// ---------------- driver ----------------
extern "C" void kernel_launch(void* const* d_in, const int* in_sizes, int n_in,
                              void* d_out, int out_size)
{
    (void)in_sizes; (void)n_in; (void)out_size;
    const float* x      = (const float*)d_in[0];
    const float* ln1_g  = (const float*)d_in[1];
    const float* ln1_b  = (const float*)d_in[2];
    const float* W_qkv  = (const float*)d_in[3];
    const float* W_proj = (const float*)d_in[4];
    const float* b_proj = (const float*)d_in[5];
    const float* ln2_g  = (const float*)d_in[6];
    const float* ln2_b  = (const float*)d_in[7];
    const float* W1     = (const float*)d_in[8];
    const float* b1     = (const float*)d_in[9];
    const float* W2     = (const float*)d_in[10];
    const float* b2     = (const float*)d_in[11];
    float* out = (float*)d_out;

    __half *h, *qkv, *att, *ffn, *wqkvT, *wprojT, *w1T, *w2T, *vT;
    float *x1;
    cudaGetSymbolAddress((void**)&h,      g_h);
    cudaGetSymbolAddress((void**)&qkv,    g_qkv);
    cudaGetSymbolAddress((void**)&att,    g_att);
    cudaGetSymbolAddress((void**)&x1,     g_x1);
    cudaGetSymbolAddress((void**)&ffn,    g_ffn);
    cudaGetSymbolAddress((void**)&wqkvT,  g_wqkvT);
    cudaGetSymbolAddress((void**)&wprojT, g_wprojT);
    cudaGetSymbolAddress((void**)&w1T,    g_w1T);
    cudaGetSymbolAddress((void**)&w2T,    g_w2T);
    cudaGetSymbolAddress((void**)&vT,     g_vT);

    const int SMG = 2 * (128 + 128) * SLDH * 2;        // 73728 bytes
    const int FLASH_SMEM = (128 + 64 + 64) * QLDH * 2; // 36864 bytes
    cudaFuncSetAttribute(mma_gemm<EPI_NONE,      true >, cudaFuncAttributeMaxDynamicSharedMemorySize, SMG);
    cudaFuncSetAttribute(mma_gemm<EPI_BIAS_RES,  false>, cudaFuncAttributeMaxDynamicSharedMemorySize, SMG);
    cudaFuncSetAttribute(mma_gemm<EPI_BIAS_GELU, true >, cudaFuncAttributeMaxDynamicSharedMemorySize, SMG);
    cudaFuncSetAttribute(flash_k, cudaFuncAttributeMaxDynamicSharedMemorySize, FLASH_SMEM);

    // 1. h = fp16(LN1(x))
    ln_k<<<BLz, 256>>>(x, ln1_g, ln1_b, h);

    // 2. weight transposes -> fp16 [N][K] K-major operands
    transpose_k<<<dim3(E3z / 32, Ez / 32, 1), 256>>>(W_qkv,  wqkvT,  E3z, Ez);
    transpose_k<<<dim3(Ez  / 32, Ez / 32, 1), 256>>>(W_proj, wprojT, Ez,  Ez);
    transpose_k<<<dim3(FFz / 32, Ez / 32, 1), 256>>>(W1,     w1T,    FFz, Ez);
    transpose_k<<<dim3(Ez  / 32, FFz / 32, 1), 256>>>(W2,    w2T,    Ez,  FFz);

    // 3. qkv = fp16(h @ W_qkv)
    mma_gemm<EPI_NONE, true><<<dim3(E3z / 128, BLz / 128, 1), 256, SMG>>>(
        h, wqkvT, qkv, nullptr, nullptr, Ez, Ez, Ez, E3z);

    // 4. vT[b,h] = V[b,h]^T  (fp16 [D][L] per head)
    transpose_h<<<dim3(Dz / 32, Lz / 32, Bz * Hz), 256>>>(
        qkv + 2 * Ez, vT, E3z, Lz, Hz,
        (long long)Lz * E3z, (long long)Dz,
        (long long)Hz * Dz * Lz, (long long)Dz * Lz);

    // 5. att = flash(Q, K, V)  — fp16 in/out, register softmax
    flash_k<<<dim3(Lz / 128, Bz * Hz), 256, FLASH_SMEM>>>(qkv, vT, att);

    // 6. x1 = x + att @ W_proj + b_proj   (fp32)
    mma_gemm<EPI_BIAS_RES, false><<<dim3(Ez / 128, BLz / 128, 1), 256, SMG>>>(
        att, wprojT, x1, b_proj, x, Ez, Ez, Ez, Ez);

    // 7. h = fp16(LN2(x1))
    ln_k<<<BLz, 256>>>(x1, ln2_g, ln2_b, h);

    // 8. ffn = fp16(gelu(h @ W1 + b1))
    mma_gemm<EPI_BIAS_GELU, true><<<dim3(FFz / 128, BLz / 128, 1), 256, SMG>>>(
        h, w1T, ffn, b1, nullptr, Ez, Ez, Ez, FFz);

    // 9. out = x1 + ffn @ W2 + b2   (fp32 final output)
    mma_gemm<EPI_BIAS_RES, false><<<dim3(Ez / 128, BLz / 128, 1), 256, SMG>>>(
        ffn, w2T, out, b2, x1, FFz, FFz, FFz, Ez);
}

// round 14
// speedup vs baseline: 3.2960x; 1.0947x over previous
#include <cuda_runtime.h>
#include <cuda_fp16.h>
#include <math.h>
#include <stdint.h>

// Problem constants
#define Bz   2
#define Lz   2048
#define Ez   1024
#define Hz   16
#define Dz   64
#define BLz  (Bz*Lz)          // 4096 rows
#define E3z  (3*Ez)           // 3072
#define FFz  (4*Ez)           // 4096

// ---------------- static device scratch (no allocations allowed) ----------------
__device__ __half g_h    [(size_t)BLz*Ez];
__device__ __half g_qkv  [(size_t)BLz*E3z];
__device__ __half g_att  [(size_t)BLz*Ez];
__device__ float  g_x1   [(size_t)BLz*Ez];
__device__ __half g_ffn  [(size_t)BLz*FFz];
__device__ __half g_wqkvT[(size_t)E3z*Ez];
__device__ __half g_wprojT[(size_t)Ez*Ez];
__device__ __half g_w1T  [(size_t)FFz*Ez];
__device__ __half g_w2T  [(size_t)Ez*FFz];
__device__ __half g_vT   [(size_t)Bz*Hz*Dz*Lz];

// ---------------- helpers ----------------
static __device__ __forceinline__ void mma_fp16(
    float* c, const uint32_t* a, const uint32_t* b)
{
    asm volatile(
        "mma.sync.aligned.m16n8k16.row.col.f32.f16.f16.f32 "
        "{%0,%1,%2,%3}, {%4,%5,%6,%7}, {%8,%9}, {%0,%1,%2,%3};"
        : "+f"(c[0]), "+f"(c[1]), "+f"(c[2]), "+f"(c[3])
        : "r"(a[0]), "r"(a[1]), "r"(a[2]), "r"(a[3]),
          "r"(b[0]), "r"(b[1]));
}
#define LDSM_X4(r0, r1, r2, r3, addr) \
    asm volatile("ldmatrix.sync.aligned.m8n8.x4.shared.b16 {%0,%1,%2,%3}, [%4];" \
        : "=r"(r0), "=r"(r1), "=r"(r2), "=r"(r3) : "r"(addr))
#define CP16(dst_u32, src_ptr) \
    asm volatile("cp.async.cg.shared.global [%0], [%1], 16;" \
                 :: "r"(dst_u32), "l"(src_ptr))
#define CP_COMMIT()  asm volatile("cp.async.commit_group;" ::: "memory")
#define CP_WAIT1()   asm volatile("cp.async.wait_group 1;" ::: "memory")
#define CP_WAIT0()   asm volatile("cp.async.wait_group 0;" ::: "memory")

// ---------------- fp16 mma.sync GEMM: 128x128 tile, BK=64, 256 threads ----------------
// ldmatrix fragment loads. A: [M,K] K-major fp16, B: [N,K] K-major fp16.
enum { EPI_NONE = 0, EPI_BIAS_RES = 1, EPI_BIAS_GELU = 2 };

#define SLDH 72   // smem row stride in halves (144 B: 16B-aligned rows, all-bank ldmatrix)

template<int EPI, bool OUT_HALF>
__global__ void __launch_bounds__(256, 2)
mma_gemm(const __half* __restrict__ A, const __half* __restrict__ B, void* __restrict__ Cv,
         const float* __restrict__ bias, const float* __restrict__ res,
         int K, int lda, int ldb, int ldc)
{
    extern __shared__ __half smh[];
    __half* Asm = smh;                         // 2 x 128 x SLDH
    __half* Bsm = smh + 2 * 128 * SLDH;        // 2 x 128 x SLDH

    int tid  = threadIdx.x;
    int lane = tid & 31;
    int wid  = tid >> 5;
    int warp_m = wid & 1;
    int warp_n = wid >> 1;

    int m0 = blockIdx.y * 128;
    int n0 = blockIdx.x * 128;

    uint32_t As_u = (uint32_t)__cvta_generic_to_shared(Asm);
    uint32_t Bs_u = (uint32_t)__cvta_generic_to_shared(Bsm);

    // ldmatrix per-thread source rows
    int lm_g = lane >> 3, lm_r = lane & 7;
    int aRow  = warp_m * 64 + (lm_g & 1) * 8 + lm_r;   // + mt*16
    int aColH = (lm_g >> 1) * 8;                       // + ks*16
    int bRow  = warp_n * 32 + (lm_g >> 1) * 8 + lm_r;  // + ntp*16
    int bColH = (lm_g & 1) * 8;                        // + ks*16

    float acc[4][4][4];
    #pragma unroll
    for (int i = 0; i < 4; i++)
        #pragma unroll
        for (int j = 0; j < 4; j++)
            #pragma unroll
            for (int k = 0; k < 4; k++) acc[i][j][k] = 0.f;

    const int slabs = K >> 6;   // BK = 64

    auto issue = [&](int s, int b) {
        int k0 = s << 6;
        #pragma unroll
        for (int i = 0; i < 4; i++) {
            int e = tid + i * 256, row = e >> 3, c8 = e & 7;
            CP16(As_u + (uint32_t)(b * 128 * SLDH + row * SLDH + c8 * 8) * 2,
                 &A[(long long)(m0 + row) * lda + k0 + c8 * 8]);
        }
        #pragma unroll
        for (int i = 0; i < 4; i++) {
            int e = tid + i * 256, row = e >> 3, c8 = e & 7;
            CP16(Bs_u + (uint32_t)(b * 128 * SLDH + row * SLDH + c8 * 8) * 2,
                 &B[(long long)(n0 + row) * ldb + k0 + c8 * 8]);
        }
    };

    issue(0, 0);
    CP_COMMIT();

    int qr = lane >> 2, qc = lane & 3;
    for (int s = 0; s < slabs; s++) {
        if (s + 1 < slabs) {
            issue(s + 1, (s + 1) & 1);
            CP_COMMIT();
            CP_WAIT1();
        } else {
            CP_WAIT0();
        }
        __syncthreads();

        uint32_t aBase = As_u + ((s & 1) * 128 * SLDH + aRow * SLDH + aColH) * 2;
        uint32_t bBase = Bs_u + ((s & 1) * 128 * SLDH + bRow * SLDH + bColH) * 2;

        #pragma unroll
        for (int ks = 0; ks < 4; ks++) {
            uint32_t af[4][4];
            #pragma unroll
            for (int mt = 0; mt < 4; mt++)
                LDSM_X4(af[mt][0], af[mt][1], af[mt][2], af[mt][3],
                        aBase + (uint32_t)(mt * 16 * SLDH + ks * 16) * 2);
            uint32_t bf[4][2];
            #pragma unroll
            for (int ntp = 0; ntp < 2; ntp++)
                LDSM_X4(bf[2 * ntp][0], bf[2 * ntp][1], bf[2 * ntp + 1][0], bf[2 * ntp + 1][1],
                        bBase + (uint32_t)(ntp * 16 * SLDH + ks * 16) * 2);
            #pragma unroll
            for (int mt = 0; mt < 4; mt++)
                #pragma unroll
                for (int nt = 0; nt < 4; nt++)
                    mma_fp16(acc[mt][nt], af[mt], bf[nt]);
        }
        __syncthreads();
    }

    float*  Cf = reinterpret_cast<float*>(Cv);
    __half* Ch = reinterpret_cast<__half*>(Cv);

    #pragma unroll
    for (int mt = 0; mt < 4; mt++) {
        #pragma unroll
        for (int nt = 0; nt < 4; nt++) {
            int gc = n0 + warp_n * 32 + nt * 8 + qc * 2;
            #pragma unroll
            for (int half_i = 0; half_i < 2; half_i++) {
                long long gr = m0 + warp_m * 64 + mt * 16 + qr + half_i * 8;
                float v0 = acc[mt][nt][half_i * 2 + 0];
                float v1 = acc[mt][nt][half_i * 2 + 1];
                if (EPI == EPI_BIAS_RES) {
                    v0 += bias[gc]     + res[gr * ldc + gc];
                    v1 += bias[gc + 1] + res[gr * ldc + gc + 1];
                }
                if (EPI == EPI_BIAS_GELU) {
                    v0 += bias[gc];
                    v1 += bias[gc + 1];
                    v0 = 0.5f * v0 * (1.f + erff(v0 * 0.70710678118654752f));
                    v1 = 0.5f * v1 * (1.f + erff(v1 * 0.70710678118654752f));
                }
                if (OUT_HALF)
                    *reinterpret_cast<__half2*>(&Ch[gr * ldc + gc]) = __floats2half2_rn(v0, v1);
                else
                    *reinterpret_cast<float2*>(&Cf[gr * ldc + gc]) = make_float2(v0, v1);
            }
        }
    }
}

// ---------------- fp16 flash attention, register softmax, ldmatrix loads ----------------
// Grid: (Lz/128, Bz*Hz). 256 threads. Each warp owns 16 query rows x ALL 64 key cols.
#define QLDH 72   // smem stride in halves for Q/K/V tiles

__global__ void __launch_bounds__(256, 2)
flash_k(const __half* __restrict__ qkv, const __half* __restrict__ vT,
        __half* __restrict__ att)
{
    extern __shared__ __half smh[];
    __half* Qs = smh;               // 128 x QLDH  (query rows x dims)
    __half* Ks = Qs + 128 * QLDH;   // 64  x QLDH  (keys x dims)
    __half* Vs = Ks + 64 * QLDH;    // 64  x QLDH  (dims x keys)

    int tid  = threadIdx.x;
    int lane = tid & 31;
    int wid  = tid >> 5;
    int qr = lane >> 2, qc = lane & 3;

    int bb = blockIdx.y >> 4;       // Hz = 16
    int hh = blockIdx.y & 15;
    int q0 = blockIdx.x * 128;
    const float CEXP = 1.4426950408889634f / 32.f;   // log2(e)/sqrt(E)

    const __half* Qg = qkv + (size_t)bb * Lz * E3z + hh * Dz;
    const __half* Kg = qkv + (size_t)bb * Lz * E3z + Ez + hh * Dz;
    const __half* Vg = vT + ((size_t)(bb * Hz + hh)) * Dz * Lz;

    uint32_t Qs_u = (uint32_t)__cvta_generic_to_shared(Qs);
    uint32_t Ks_u = (uint32_t)__cvta_generic_to_shared(Ks);
    uint32_t Vs_u = (uint32_t)__cvta_generic_to_shared(Vs);

    int lm_g = lane >> 3, lm_r = lane & 7;
    // A-pattern (Q): rows wid*16 + {0|8} + lm_r, cols {0|8}
    uint32_t qBase = Qs_u + (uint32_t)((wid * 16 + (lm_g & 1) * 8 + lm_r) * QLDH
                                        + (lm_g >> 1) * 8) * 2;
    // B-pattern (K and V): rows {0|8} + lm_r (+ntp*16), cols {0|8} (+ks*16)
    uint32_t kvOff = (uint32_t)(((lm_g >> 1) * 8 + lm_r) * QLDH + (lm_g & 1) * 8) * 2;
    uint32_t kBase = Ks_u + kvOff;
    uint32_t vBase = Vs_u + kvOff;

    // Q tile (128 x 64 halves), loaded once
    #pragma unroll
    for (int i = 0; i < 4; i++) {
        int e = tid + i * 256, row = e >> 3, c8 = e & 7;
        *reinterpret_cast<float4*>(&Qs[row * QLDH + c8 * 8]) =
            *reinterpret_cast<const float4*>(&Qg[(size_t)(q0 + row) * E3z + c8 * 8]);
    }

    float o[8][4];
    #pragma unroll
    for (int nt = 0; nt < 8; nt++)
        #pragma unroll
        for (int k = 0; k < 4; k++) o[nt][k] = 0.f;
    float m0 = -INFINITY, m1 = -INFINITY, l0 = 0.f, l1 = 0.f;

    for (int kt = 0; kt < 32; kt++) {
        __syncthreads();

        // K tile: 64 keys x 64 dims
        #pragma unroll
        for (int i = 0; i < 2; i++) {
            int e = tid + i * 256, row = e >> 3, c8 = e & 7;
            *reinterpret_cast<float4*>(&Ks[row * QLDH + c8 * 8]) =
                *reinterpret_cast<const float4*>(&Kg[(size_t)(kt * 64 + row) * E3z + c8 * 8]);
        }
        // V tile: 64 dims x 64 keys (dim-major from vT)
        #pragma unroll
        for (int i = 0; i < 2; i++) {
            int e = tid + i * 256, row = e >> 3, c8 = e & 7;
            *reinterpret_cast<float4*>(&Vs[row * QLDH + c8 * 8]) =
                *reinterpret_cast<const float4*>(&Vg[(size_t)row * Lz + kt * 64 + c8 * 8]);
        }
        __syncthreads();

        // ---- S = Q @ K^T : this warp's 16 rows x 64 cols ----
        float s[8][4];
        #pragma unroll
        for (int nt = 0; nt < 8; nt++)
            #pragma unroll
            for (int k = 0; k < 4; k++) s[nt][k] = 0.f;

        #pragma unroll
        for (int ks = 0; ks < 4; ks++) {
            uint32_t a[4];
            LDSM_X4(a[0], a[1], a[2], a[3], qBase + (uint32_t)(ks * 16) * 2);
            uint32_t b[8][2];
            #pragma unroll
            for (int ntp = 0; ntp < 4; ntp++)
                LDSM_X4(b[2 * ntp][0], b[2 * ntp][1], b[2 * ntp + 1][0], b[2 * ntp + 1][1],
                        kBase + (uint32_t)(ntp * 16 * QLDH + ks * 16) * 2);
            #pragma unroll
            for (int nt = 0; nt < 8; nt++)
                mma_fp16(s[nt], a, b[nt]);
        }

        // ---- register online softmax (rows qr, qr+8; reduce over quad) ----
        float mx0 = -INFINITY, mx1 = -INFINITY;
        #pragma unroll
        for (int nt = 0; nt < 8; nt++) {
            mx0 = fmaxf(mx0, fmaxf(s[nt][0], s[nt][1]));
            mx1 = fmaxf(mx1, fmaxf(s[nt][2], s[nt][3]));
        }
        mx0 = fmaxf(mx0, __shfl_xor_sync(0xffffffffu, mx0, 1));
        mx0 = fmaxf(mx0, __shfl_xor_sync(0xffffffffu, mx0, 2));
        mx1 = fmaxf(mx1, __shfl_xor_sync(0xffffffffu, mx1, 1));
        mx1 = fmaxf(mx1, __shfl_xor_sync(0xffffffffu, mx1, 2));

        float mn0 = fmaxf(m0, mx0), mn1 = fmaxf(m1, mx1);
        float f0 = exp2f((m0 - mn0) * CEXP);
        float f1 = exp2f((m1 - mn1) * CEXP);

        float sum0 = 0.f, sum1 = 0.f;
        uint32_t p0[8], p1[8];
        #pragma unroll
        for (int nt = 0; nt < 8; nt++) {
            float e0 = exp2f((s[nt][0] - mn0) * CEXP);
            float e1 = exp2f((s[nt][1] - mn0) * CEXP);
            float e2 = exp2f((s[nt][2] - mn1) * CEXP);
            float e3 = exp2f((s[nt][3] - mn1) * CEXP);
            sum0 += e0 + e1;
            sum1 += e2 + e3;
            __half2 h0 = __floats2half2_rn(e0, e1);
            __half2 h1 = __floats2half2_rn(e2, e3);
            p0[nt] = *reinterpret_cast<uint32_t*>(&h0);
            p1[nt] = *reinterpret_cast<uint32_t*>(&h1);
        }
        sum0 += __shfl_xor_sync(0xffffffffu, sum0, 1);
        sum0 += __shfl_xor_sync(0xffffffffu, sum0, 2);
        sum1 += __shfl_xor_sync(0xffffffffu, sum1, 1);
        sum1 += __shfl_xor_sync(0xffffffffu, sum1, 2);

        l0 = l0 * f0 + sum0;  m0 = mn0;
        l1 = l1 * f1 + sum1;  m1 = mn1;

        #pragma unroll
        for (int nt = 0; nt < 8; nt++) {
            o[nt][0] *= f0; o[nt][1] *= f0;
            o[nt][2] *= f1; o[nt][3] *= f1;
        }

        // ---- O += P @ V : P fragments direct from registers ----
        #pragma unroll
        for (int kt2 = 0; kt2 < 4; kt2++) {
            uint32_t a[4] = { p0[2 * kt2], p1[2 * kt2], p0[2 * kt2 + 1], p1[2 * kt2 + 1] };
            uint32_t b[8][2];
            #pragma unroll
            for (int ntp = 0; ntp < 4; ntp++)
                LDSM_X4(b[2 * ntp][0], b[2 * ntp][1], b[2 * ntp + 1][0], b[2 * ntp + 1][1],
                        vBase + (uint32_t)(ntp * 16 * QLDH + kt2 * 16) * 2);
            #pragma unroll
            for (int nt = 0; nt < 8; nt++)
                mma_fp16(o[nt], a, b[nt]);
        }
    }

    // ---- finalize ----
    float i0 = 1.f / l0, i1 = 1.f / l1;
    size_t r0g = (size_t)bb * Lz + q0 + wid * 16 + qr;
    #pragma unroll
    for (int nt = 0; nt < 8; nt++) {
        int col = hh * Dz + nt * 8 + 2 * qc;
        *reinterpret_cast<__half2*>(&att[r0g * Ez + col]) =
            __floats2half2_rn(o[nt][0] * i0, o[nt][1] * i0);
        *reinterpret_cast<__half2*>(&att[(r0g + 8) * Ez + col]) =
            __floats2half2_rn(o[nt][2] * i1, o[nt][3] * i1);
    }
}

// ---------------- fp32 -> fp16 tiled transpose (weights) ----------------
__global__ void __launch_bounds__(256) transpose_k(
    const float* __restrict__ src, __half* __restrict__ dst, int lds, int ldd)
{
    __shared__ float t[32][33];
    int r0 = blockIdx.y * 32, c0 = blockIdx.x * 32;
    int x = threadIdx.x & 31, y4 = (threadIdx.x >> 5) * 4;
    #pragma unroll
    for (int i = 0; i < 4; i++)
        t[y4 + i][x] = src[(long long)(r0 + y4 + i) * lds + c0 + x];
    __syncthreads();
    #pragma unroll
    for (int i = 0; i < 4; i++)
        dst[(long long)(c0 + y4 + i) * ldd + r0 + x] = __float2half_rn(t[x][y4 + i]);
}

// ---------------- fp16 -> fp16 tiled transpose (V per head) ----------------
__global__ void __launch_bounds__(256) transpose_h(
    const __half* __restrict__ src, __half* __restrict__ dst,
    int lds, int ldd, int NH,
    long long sSb, long long sSh, long long sDb, long long sDh)
{
    __shared__ __half t[32][34];
    int z = blockIdx.z, bb = z / NH, hh = z % NH;
    src += bb * sSb + hh * sSh;
    dst += bb * sDb + hh * sDh;
    int r0 = blockIdx.y * 32, c0 = blockIdx.x * 32;
    int x = threadIdx.x & 31, y4 = (threadIdx.x >> 5) * 4;
    #pragma unroll
    for (int i = 0; i < 4; i++)
        t[y4 + i][x] = src[(long long)(r0 + y4 + i) * lds + c0 + x];
    __syncthreads();
    #pragma unroll
    for (int i = 0; i < 4; i++)
        dst[(long long)(c0 + y4 + i) * ldd + r0 + x] = t[x][y4 + i];
}

// ---------------- LayerNorm, fp16 output ----------------
__global__ __launch_bounds__(256) void ln_k(
    const float* __restrict__ x, const float* __restrict__ g,
    const float* __restrict__ b, __half* __restrict__ y)
{
    __shared__ float sh_s[8];
    __shared__ float sh_q[8];
    long long row = blockIdx.x;
    const float* xr = x + row * Ez;
    int t = threadIdx.x;

    float4 v = reinterpret_cast<const float4*>(xr)[t];
    float s  = v.x + v.y + v.z + v.w;
    float sq = v.x * v.x + v.y * v.y + v.z * v.z + v.w * v.w;
    #pragma unroll
    for (int o = 16; o > 0; o >>= 1) {
        s  += __shfl_down_sync(0xffffffffu, s,  o);
        sq += __shfl_down_sync(0xffffffffu, sq, o);
    }
    int warp = t >> 5, lane = t & 31;
    if (lane == 0) { sh_s[warp] = s; sh_q[warp] = sq; }
    __syncthreads();
    if (warp == 0) {
        s  = (lane < 8) ? sh_s[lane] : 0.f;
        sq = (lane < 8) ? sh_q[lane] : 0.f;
        #pragma unroll
        for (int o = 4; o > 0; o >>= 1) {
            s  += __shfl_down_sync(0xffffffffu, s,  o);
            sq += __shfl_down_sync(0xffffffffu, sq, o);
        }
        if (lane == 0) { sh_s[0] = s; sh_q[0] = sq; }
    }
    __syncthreads();
    float mu  = sh_s[0] * (1.f / Ez);
    float var = sh_q[0] * (1.f / Ez) - mu * mu;
    float inv = rsqrtf(var + 1e-5f);

    float4 gg = reinterpret_cast<const float4*>(g)[t];
    float4 bb = reinterpret_cast<const float4*>(b)[t];
    __half2 o0 = __floats2half2_rn((v.x - mu) * inv * gg.x + bb.x,
                                   (v.y - mu) * inv * gg.y + bb.y);
    __half2 o1 = __floats2half2_rn((v.z - mu) * inv * gg.z + bb.z,
                                   (v.w - mu) * inv * gg.w + bb.w);
    uint2 pk = make_uint2(*reinterpret_cast<uint32_t*>(&o0),
                          *reinterpret_cast<uint32_t*>(&o1));
    reinterpret_cast<uint2*>(y + row * Ez)[t] = pk;
}

// ---------------- driver ----------------
extern "C" void kernel_launch(void* const* d_in, const int* in_sizes, int n_in,
                              void* d_out, int out_size)
{
    (void)in_sizes; (void)n_in; (void)out_size;
    const float* x      = (const float*)d_in[0];
    const float* ln1_g  = (const float*)d_in[1];
    const float* ln1_b  = (const float*)d_in[2];
    const float* W_qkv  = (const float*)d_in[3];
    const float* W_proj = (const float*)d_in[4];
    const float* b_proj = (const float*)d_in[5];
    const float* ln2_g  = (const float*)d_in[6];
    const float* ln2_b  = (const float*)d_in[7];
    const float* W1     = (const float*)d_in[8];
    const float* b1     = (const float*)d_in[9];
    const float* W2     = (const float*)d_in[10];
    const float* b2     = (const float*)d_in[11];
    float* out = (float*)d_out;

    __half *h, *qkv, *att, *ffn, *wqkvT, *wprojT, *w1T, *w2T, *vT;
    float *x1;
    cudaGetSymbolAddress((void**)&h,      g_h);
    cudaGetSymbolAddress((void**)&qkv,    g_qkv);
    cudaGetSymbolAddress((void**)&att,    g_att);
    cudaGetSymbolAddress((void**)&x1,     g_x1);
    cudaGetSymbolAddress((void**)&ffn,    g_ffn);
    cudaGetSymbolAddress((void**)&wqkvT,  g_wqkvT);
    cudaGetSymbolAddress((void**)&wprojT, g_wprojT);
    cudaGetSymbolAddress((void**)&w1T,    g_w1T);
    cudaGetSymbolAddress((void**)&w2T,    g_w2T);
    cudaGetSymbolAddress((void**)&vT,     g_vT);

    const int SMG = 2 * (128 + 128) * SLDH * 2;        // 73728 bytes
    const int FLASH_SMEM = (128 + 64 + 64) * QLDH * 2; // 36864 bytes
    cudaFuncSetAttribute(mma_gemm<EPI_NONE,      true >, cudaFuncAttributeMaxDynamicSharedMemorySize, SMG);
    cudaFuncSetAttribute(mma_gemm<EPI_BIAS_RES,  false>, cudaFuncAttributeMaxDynamicSharedMemorySize, SMG);
    cudaFuncSetAttribute(mma_gemm<EPI_BIAS_GELU, true >, cudaFuncAttributeMaxDynamicSharedMemorySize, SMG);
    cudaFuncSetAttribute(flash_k, cudaFuncAttributeMaxDynamicSharedMemorySize, FLASH_SMEM);

    // 1. h = fp16(LN1(x))
    ln_k<<<BLz, 256>>>(x, ln1_g, ln1_b, h);

    // 2. weight transposes -> fp16 [N][K] K-major operands
    transpose_k<<<dim3(E3z / 32, Ez / 32, 1), 256>>>(W_qkv,  wqkvT,  E3z, Ez);
    transpose_k<<<dim3(Ez  / 32, Ez / 32, 1), 256>>>(W_proj, wprojT, Ez,  Ez);
    transpose_k<<<dim3(FFz / 32, Ez / 32, 1), 256>>>(W1,     w1T,    FFz, Ez);
    transpose_k<<<dim3(Ez  / 32, FFz / 32, 1), 256>>>(W2,    w2T,    Ez,  FFz);

    // 3. qkv = fp16(h @ W_qkv)
    mma_gemm<EPI_NONE, true><<<dim3(E3z / 128, BLz / 128, 1), 256, SMG>>>(
        h, wqkvT, qkv, nullptr, nullptr, Ez, Ez, Ez, E3z);

    // 4. vT[b,h] = V[b,h]^T  (fp16 [D][L] per head)
    transpose_h<<<dim3(Dz / 32, Lz / 32, Bz * Hz), 256>>>(
        qkv + 2 * Ez, vT, E3z, Lz, Hz,
        (long long)Lz * E3z, (long long)Dz,
        (long long)Hz * Dz * Lz, (long long)Dz * Lz);

    // 5. att = flash(Q, K, V)  — fp16, register softmax, ldmatrix
    flash_k<<<dim3(Lz / 128, Bz * Hz), 256, FLASH_SMEM>>>(qkv, vT, att);

    // 6. x1 = x + att @ W_proj + b_proj   (fp32)
    mma_gemm<EPI_BIAS_RES, false><<<dim3(Ez / 128, BLz / 128, 1), 256, SMG>>>(
        att, wprojT, x1, b_proj, x, Ez, Ez, Ez, Ez);

    // 7. h = fp16(LN2(x1))
    ln_k<<<BLz, 256>>>(x1, ln2_g, ln2_b, h);

    // 8. ffn = fp16(gelu(h @ W1 + b1))
    mma_gemm<EPI_BIAS_GELU, true><<<dim3(FFz / 128, BLz / 128, 1), 256, SMG>>>(
        h, w1T, ffn, b1, nullptr, Ez, Ez, Ez, FFz);

    // 9. out = x1 + ffn @ W2 + b2   (fp32 final output)
    mma_gemm<EPI_BIAS_RES, false><<<dim3(Ez / 128, BLz / 128, 1), 256, SMG>>>(
        ffn, w2T, out, b2, x1, FFz, FFz, FFz, Ez);
}

// round 15
// speedup vs baseline: 3.3471x; 1.0155x over previous
#include <cuda_runtime.h>
#include <cuda_fp16.h>
#include <math.h>
#include <stdint.h>

// Problem constants
#define Bz   2
#define Lz   2048
#define Ez   1024
#define Hz   16
#define Dz   64
#define BLz  (Bz*Lz)          // 4096 rows
#define E3z  (3*Ez)           // 3072
#define FFz  (4*Ez)           // 4096

// ---------------- static device scratch (no allocations allowed) ----------------
__device__ __half g_h    [(size_t)BLz*Ez];
__device__ __half g_qkv  [(size_t)BLz*E3z];
__device__ __half g_att  [(size_t)BLz*Ez];
__device__ float  g_x1   [(size_t)BLz*Ez];
__device__ __half g_ffn  [(size_t)BLz*FFz];
__device__ __half g_wqkvT[(size_t)E3z*Ez];
__device__ __half g_wprojT[(size_t)Ez*Ez];
__device__ __half g_w1T  [(size_t)FFz*Ez];
__device__ __half g_w2T  [(size_t)Ez*FFz];

// ---------------- helpers ----------------
static __device__ __forceinline__ void mma_fp16(
    float* c, const uint32_t* a, const uint32_t* b)
{
    asm volatile(
        "mma.sync.aligned.m16n8k16.row.col.f32.f16.f16.f32 "
        "{%0,%1,%2,%3}, {%4,%5,%6,%7}, {%8,%9}, {%0,%1,%2,%3};"
        : "+f"(c[0]), "+f"(c[1]), "+f"(c[2]), "+f"(c[3])
        : "r"(a[0]), "r"(a[1]), "r"(a[2]), "r"(a[3]),
          "r"(b[0]), "r"(b[1]));
}
#define LDSM_X4(r0, r1, r2, r3, addr) \
    asm volatile("ldmatrix.sync.aligned.m8n8.x4.shared.b16 {%0,%1,%2,%3}, [%4];" \
        : "=r"(r0), "=r"(r1), "=r"(r2), "=r"(r3) : "r"(addr))
#define LDSM_X4_T(r0, r1, r2, r3, addr) \
    asm volatile("ldmatrix.sync.aligned.m8n8.x4.trans.shared.b16 {%0,%1,%2,%3}, [%4];" \
        : "=r"(r0), "=r"(r1), "=r"(r2), "=r"(r3) : "r"(addr))
#define CP16(dst_u32, src_ptr) \
    asm volatile("cp.async.cg.shared.global [%0], [%1], 16;" \
                 :: "r"(dst_u32), "l"(src_ptr))
#define CP_COMMIT()  asm volatile("cp.async.commit_group;" ::: "memory")
#define CP_WAIT1()   asm volatile("cp.async.wait_group 1;" ::: "memory")
#define CP_WAIT0()   asm volatile("cp.async.wait_group 0;" ::: "memory")

// ---------------- fp16 mma.sync GEMM: 128x128 tile, BK=64, 3-stage pipeline ----------------
enum { EPI_NONE = 0, EPI_BIAS_RES = 1, EPI_BIAS_GELU = 2 };

#define SLDH 72   // smem row stride in halves

template<int EPI, bool OUT_HALF>
__global__ void __launch_bounds__(256, 2)
mma_gemm(const __half* __restrict__ A, const __half* __restrict__ B, void* __restrict__ Cv,
         const float* __restrict__ bias, const float* __restrict__ res,
         int K, int lda, int ldb, int ldc)
{
    extern __shared__ __half smh[];
    // 3 stages, each: A 128xSLDH then B 128xSLDH
    const int STG = 2 * 128 * SLDH;

    int tid  = threadIdx.x;
    int lane = tid & 31;
    int wid  = tid >> 5;
    int warp_m = wid & 1;
    int warp_n = wid >> 1;

    int m0 = blockIdx.y * 128;
    int n0 = blockIdx.x * 128;

    uint32_t Sm_u = (uint32_t)__cvta_generic_to_shared(smh);

    int lm_g = lane >> 3, lm_r = lane & 7;
    int aRow  = warp_m * 64 + (lm_g & 1) * 8 + lm_r;
    int aColH = (lm_g >> 1) * 8;
    int bRow  = warp_n * 32 + (lm_g >> 1) * 8 + lm_r;
    int bColH = (lm_g & 1) * 8;

    float acc[4][4][4];
    #pragma unroll
    for (int i = 0; i < 4; i++)
        #pragma unroll
        for (int j = 0; j < 4; j++)
            #pragma unroll
            for (int k = 0; k < 4; k++) acc[i][j][k] = 0.f;

    const int slabs = K >> 6;   // BK = 64

    auto issue = [&](int s, int buf) {
        int k0 = s << 6;
        uint32_t base = Sm_u + (uint32_t)(buf * STG) * 2;
        #pragma unroll
        for (int i = 0; i < 4; i++) {
            int e = tid + i * 256, row = e >> 3, c8 = e & 7;
            CP16(base + (uint32_t)(row * SLDH + c8 * 8) * 2,
                 &A[(long long)(m0 + row) * lda + k0 + c8 * 8]);
        }
        #pragma unroll
        for (int i = 0; i < 4; i++) {
            int e = tid + i * 256, row = e >> 3, c8 = e & 7;
            CP16(base + (uint32_t)(128 * SLDH + row * SLDH + c8 * 8) * 2,
                 &B[(long long)(n0 + row) * ldb + k0 + c8 * 8]);
        }
    };

    issue(0, 0); CP_COMMIT();
    issue(1, 1); CP_COMMIT();

    int qr = lane >> 2, qc = lane & 3;
    int cur = 0;
    for (int s = 0; s < slabs; s++) {
        if (s + 1 < slabs) { CP_WAIT1(); } else { CP_WAIT0(); }
        __syncthreads();   // buffer `cur` ready for all; all warps done with buffer cur+2 (mod 3)

        int nxt = cur + 2; if (nxt >= 3) nxt -= 3;
        if (s + 2 < slabs) { issue(s + 2, nxt); CP_COMMIT(); }

        uint32_t aBase = Sm_u + (uint32_t)(cur * STG + aRow * SLDH + aColH) * 2;
        uint32_t bBase = Sm_u + (uint32_t)(cur * STG + 128 * SLDH + bRow * SLDH + bColH) * 2;

        #pragma unroll
        for (int ks = 0; ks < 4; ks++) {
            uint32_t af[4][4];
            #pragma unroll
            for (int mt = 0; mt < 4; mt++)
                LDSM_X4(af[mt][0], af[mt][1], af[mt][2], af[mt][3],
                        aBase + (uint32_t)(mt * 16 * SLDH + ks * 16) * 2);
            uint32_t bf[4][2];
            #pragma unroll
            for (int ntp = 0; ntp < 2; ntp++)
                LDSM_X4(bf[2 * ntp][0], bf[2 * ntp][1], bf[2 * ntp + 1][0], bf[2 * ntp + 1][1],
                        bBase + (uint32_t)(ntp * 16 * SLDH + ks * 16) * 2);
            #pragma unroll
            for (int mt = 0; mt < 4; mt++)
                #pragma unroll
                for (int nt = 0; nt < 4; nt++)
                    mma_fp16(acc[mt][nt], af[mt], bf[nt]);
        }
        cur = cur + 1; if (cur == 3) cur = 0;
    }

    float*  Cf = reinterpret_cast<float*>(Cv);
    __half* Ch = reinterpret_cast<__half*>(Cv);

    #pragma unroll
    for (int mt = 0; mt < 4; mt++) {
        #pragma unroll
        for (int nt = 0; nt < 4; nt++) {
            int gc = n0 + warp_n * 32 + nt * 8 + qc * 2;
            #pragma unroll
            for (int half_i = 0; half_i < 2; half_i++) {
                long long gr = m0 + warp_m * 64 + mt * 16 + qr + half_i * 8;
                float v0 = acc[mt][nt][half_i * 2 + 0];
                float v1 = acc[mt][nt][half_i * 2 + 1];
                if (EPI == EPI_BIAS_RES) {
                    v0 += bias[gc]     + res[gr * ldc + gc];
                    v1 += bias[gc + 1] + res[gr * ldc + gc + 1];
                }
                if (EPI == EPI_BIAS_GELU) {
                    v0 += bias[gc];
                    v1 += bias[gc + 1];
                    v0 = 0.5f * v0 * (1.f + erff(v0 * 0.70710678118654752f));
                    v1 = 0.5f * v1 * (1.f + erff(v1 * 0.70710678118654752f));
                }
                if (OUT_HALF)
                    *reinterpret_cast<__half2*>(&Ch[gr * ldc + gc]) = __floats2half2_rn(v0, v1);
                else
                    *reinterpret_cast<float2*>(&Cf[gr * ldc + gc]) = make_float2(v0, v1);
            }
        }
    }
}

// ---------------- fp16 flash attention: register softmax, ldmatrix(+trans V) ----------------
// Grid: (Lz/128, Bz*Hz). 256 threads. Each warp: 16 query rows x all 64 key cols.
// V consumed DIRECTLY from qkv (key-major) via ldmatrix.trans — no vT buffer.
#define QLDH 72

__global__ void __launch_bounds__(256, 2)
flash_k(const __half* __restrict__ qkv, __half* __restrict__ att)
{
    extern __shared__ __half smh[];
    __half* Qs = smh;               // 128 x QLDH  (query rows x dims)
    __half* Ks = Qs + 128 * QLDH;   // 64  x QLDH  (keys x dims)
    __half* Vs = Ks + 64 * QLDH;    // 64  x QLDH  (keys x dims)

    int tid  = threadIdx.x;
    int lane = tid & 31;
    int wid  = tid >> 5;
    int qr = lane >> 2, qc = lane & 3;

    int bb = blockIdx.y >> 4;       // Hz = 16
    int hh = blockIdx.y & 15;
    int q0 = blockIdx.x * 128;
    const float CEXP = 1.4426950408889634f / 32.f;   // log2(e)/sqrt(E)

    const __half* Qg = qkv + (size_t)bb * Lz * E3z + hh * Dz;
    const __half* Kg = qkv + (size_t)bb * Lz * E3z + Ez + hh * Dz;
    const __half* Vg = qkv + (size_t)bb * Lz * E3z + 2 * Ez + hh * Dz;

    uint32_t Qs_u = (uint32_t)__cvta_generic_to_shared(Qs);
    uint32_t Ks_u = (uint32_t)__cvta_generic_to_shared(Ks);
    uint32_t Vs_u = (uint32_t)__cvta_generic_to_shared(Vs);

    int lm_g = lane >> 3, lm_r = lane & 7;
    // A-pattern (Q): rows wid*16 + {0|8} + lm_r, cols {0|8}
    uint32_t qBase = Qs_u + (uint32_t)((wid * 16 + (lm_g & 1) * 8 + lm_r) * QLDH
                                        + (lm_g >> 1) * 8) * 2;
    // B-pattern non-trans (K): rows {0|8}+lm_r (+ntp*16 along n=key), cols {0|8} (+ks*16 along k=dim)
    uint32_t kBase = Ks_u + (uint32_t)(((lm_g >> 1) * 8 + lm_r) * QLDH + (lm_g & 1) * 8) * 2;
    // B-pattern trans (V): source rows = keys (k): {0|8}+lm_r (+kt2*16), cols = dims (n): {0|8} (+ntp*16)
    uint32_t vBase = Vs_u + (uint32_t)(((lm_g & 1) * 8 + lm_r) * QLDH + (lm_g >> 1) * 8) * 2;

    // Q tile (128 x 64 halves), loaded once
    #pragma unroll
    for (int i = 0; i < 4; i++) {
        int e = tid + i * 256, row = e >> 3, c8 = e & 7;
        *reinterpret_cast<float4*>(&Qs[row * QLDH + c8 * 8]) =
            *reinterpret_cast<const float4*>(&Qg[(size_t)(q0 + row) * E3z + c8 * 8]);
    }

    float o[8][4];
    #pragma unroll
    for (int nt = 0; nt < 8; nt++)
        #pragma unroll
        for (int k = 0; k < 4; k++) o[nt][k] = 0.f;
    float m0 = -INFINITY, m1 = -INFINITY, l0 = 0.f, l1 = 0.f;

    for (int kt = 0; kt < 32; kt++) {
        __syncthreads();

        // K tile: 64 keys x 64 dims
        #pragma unroll
        for (int i = 0; i < 2; i++) {
            int e = tid + i * 256, row = e >> 3, c8 = e & 7;
            *reinterpret_cast<float4*>(&Ks[row * QLDH + c8 * 8]) =
                *reinterpret_cast<const float4*>(&Kg[(size_t)(kt * 64 + row) * E3z + c8 * 8]);
        }
        // V tile: 64 keys x 64 dims (key-major, straight from qkv)
        #pragma unroll
        for (int i = 0; i < 2; i++) {
            int e = tid + i * 256, row = e >> 3, c8 = e & 7;
            *reinterpret_cast<float4*>(&Vs[row * QLDH + c8 * 8]) =
                *reinterpret_cast<const float4*>(&Vg[(size_t)(kt * 64 + row) * E3z + c8 * 8]);
        }
        __syncthreads();

        // ---- S = Q @ K^T ----
        float s[8][4];
        #pragma unroll
        for (int nt = 0; nt < 8; nt++)
            #pragma unroll
            for (int k = 0; k < 4; k++) s[nt][k] = 0.f;

        #pragma unroll
        for (int ks = 0; ks < 4; ks++) {
            uint32_t a[4];
            LDSM_X4(a[0], a[1], a[2], a[3], qBase + (uint32_t)(ks * 16) * 2);
            uint32_t b[8][2];
            #pragma unroll
            for (int ntp = 0; ntp < 4; ntp++)
                LDSM_X4(b[2 * ntp][0], b[2 * ntp][1], b[2 * ntp + 1][0], b[2 * ntp + 1][1],
                        kBase + (uint32_t)(ntp * 16 * QLDH + ks * 16) * 2);
            #pragma unroll
            for (int nt = 0; nt < 8; nt++)
                mma_fp16(s[nt], a, b[nt]);
        }

        // ---- register online softmax ----
        float mx0 = -INFINITY, mx1 = -INFINITY;
        #pragma unroll
        for (int nt = 0; nt < 8; nt++) {
            mx0 = fmaxf(mx0, fmaxf(s[nt][0], s[nt][1]));
            mx1 = fmaxf(mx1, fmaxf(s[nt][2], s[nt][3]));
        }
        mx0 = fmaxf(mx0, __shfl_xor_sync(0xffffffffu, mx0, 1));
        mx0 = fmaxf(mx0, __shfl_xor_sync(0xffffffffu, mx0, 2));
        mx1 = fmaxf(mx1, __shfl_xor_sync(0xffffffffu, mx1, 1));
        mx1 = fmaxf(mx1, __shfl_xor_sync(0xffffffffu, mx1, 2));

        float mn0 = fmaxf(m0, mx0), mn1 = fmaxf(m1, mx1);
        float f0 = exp2f((m0 - mn0) * CEXP);
        float f1 = exp2f((m1 - mn1) * CEXP);

        float sum0 = 0.f, sum1 = 0.f;
        uint32_t p0[8], p1[8];
        #pragma unroll
        for (int nt = 0; nt < 8; nt++) {
            float e0 = exp2f((s[nt][0] - mn0) * CEXP);
            float e1 = exp2f((s[nt][1] - mn0) * CEXP);
            float e2 = exp2f((s[nt][2] - mn1) * CEXP);
            float e3 = exp2f((s[nt][3] - mn1) * CEXP);
            sum0 += e0 + e1;
            sum1 += e2 + e3;
            __half2 h0 = __floats2half2_rn(e0, e1);
            __half2 h1 = __floats2half2_rn(e2, e3);
            p0[nt] = *reinterpret_cast<uint32_t*>(&h0);
            p1[nt] = *reinterpret_cast<uint32_t*>(&h1);
        }
        sum0 += __shfl_xor_sync(0xffffffffu, sum0, 1);
        sum0 += __shfl_xor_sync(0xffffffffu, sum0, 2);
        sum1 += __shfl_xor_sync(0xffffffffu, sum1, 1);
        sum1 += __shfl_xor_sync(0xffffffffu, sum1, 2);

        l0 = l0 * f0 + sum0;  m0 = mn0;
        l1 = l1 * f1 + sum1;  m1 = mn1;

        #pragma unroll
        for (int nt = 0; nt < 8; nt++) {
            o[nt][0] *= f0; o[nt][1] *= f0;
            o[nt][2] *= f1; o[nt][3] *= f1;
        }

        // ---- O += P @ V : V B-fragments via ldmatrix.trans from key-major tile ----
        #pragma unroll
        for (int kt2 = 0; kt2 < 4; kt2++) {
            uint32_t a[4] = { p0[2 * kt2], p1[2 * kt2], p0[2 * kt2 + 1], p1[2 * kt2 + 1] };
            uint32_t b[8][2];
            #pragma unroll
            for (int ntp = 0; ntp < 4; ntp++)
                LDSM_X4_T(b[2 * ntp][0], b[2 * ntp][1], b[2 * ntp + 1][0], b[2 * ntp + 1][1],
                          vBase + (uint32_t)(kt2 * 16 * QLDH + ntp * 16) * 2);
            #pragma unroll
            for (int nt = 0; nt < 8; nt++)
                mma_fp16(o[nt], a, b[nt]);
        }
    }

    // ---- finalize ----
    float i0 = 1.f / l0, i1 = 1.f / l1;
    size_t r0g = (size_t)bb * Lz + q0 + wid * 16 + qr;
    #pragma unroll
    for (int nt = 0; nt < 8; nt++) {
        int col = hh * Dz + nt * 8 + 2 * qc;
        *reinterpret_cast<__half2*>(&att[r0g * Ez + col]) =
            __floats2half2_rn(o[nt][0] * i0, o[nt][1] * i0);
        *reinterpret_cast<__half2*>(&att[(r0g + 8) * Ez + col]) =
            __floats2half2_rn(o[nt][2] * i1, o[nt][3] * i1);
    }
}

// ---------------- fused prep: LN1 + all 4 weight transposes in ONE launch ----------------
static __device__ __forceinline__ void dev_transpose(
    const float* __restrict__ src, __half* __restrict__ dst,
    int lds, int ldd, int bx, int by, float (*t)[33])
{
    int r0 = by * 32, c0 = bx * 32;
    int x = threadIdx.x & 31, y4 = (threadIdx.x >> 5) * 4;
    #pragma unroll
    for (int i = 0; i < 4; i++)
        t[y4 + i][x] = src[(long long)(r0 + y4 + i) * lds + c0 + x];
    __syncthreads();
    #pragma unroll
    for (int i = 0; i < 4; i++)
        dst[(long long)(c0 + y4 + i) * ldd + r0 + x] = __float2half_rn(t[x][y4 + i]);
}

static __device__ __forceinline__ void dev_ln(
    const float* __restrict__ x, const float* __restrict__ g,
    const float* __restrict__ b, __half* __restrict__ y, long long row,
    float* sh_s, float* sh_q)
{
    const float* xr = x + row * Ez;
    int t = threadIdx.x;

    float4 v = reinterpret_cast<const float4*>(xr)[t];
    float s  = v.x + v.y + v.z + v.w;
    float sq = v.x * v.x + v.y * v.y + v.z * v.z + v.w * v.w;
    #pragma unroll
    for (int o = 16; o > 0; o >>= 1) {
        s  += __shfl_down_sync(0xffffffffu, s,  o);
        sq += __shfl_down_sync(0xffffffffu, sq, o);
    }
    int warp = t >> 5, lane = t & 31;
    if (lane == 0) { sh_s[warp] = s; sh_q[warp] = sq; }
    __syncthreads();
    if (warp == 0) {
        s  = (lane < 8) ? sh_s[lane] : 0.f;
        sq = (lane < 8) ? sh_q[lane] : 0.f;
        #pragma unroll
        for (int o = 4; o > 0; o >>= 1) {
            s  += __shfl_down_sync(0xffffffffu, s,  o);
            sq += __shfl_down_sync(0xffffffffu, sq, o);
        }
        if (lane == 0) { sh_s[0] = s; sh_q[0] = sq; }
    }
    __syncthreads();
    float mu  = sh_s[0] * (1.f / Ez);
    float var = sh_q[0] * (1.f / Ez) - mu * mu;
    float inv = rsqrtf(var + 1e-5f);

    float4 gg = reinterpret_cast<const float4*>(g)[t];
    float4 bb = reinterpret_cast<const float4*>(b)[t];
    __half2 o0 = __floats2half2_rn((v.x - mu) * inv * gg.x + bb.x,
                                   (v.y - mu) * inv * gg.y + bb.y);
    __half2 o1 = __floats2half2_rn((v.z - mu) * inv * gg.z + bb.z,
                                   (v.w - mu) * inv * gg.w + bb.w);
    uint2 pk = make_uint2(*reinterpret_cast<uint32_t*>(&o0),
                          *reinterpret_cast<uint32_t*>(&o1));
    reinterpret_cast<uint2*>(y + row * Ez)[t] = pk;
}

__global__ void __launch_bounds__(256) prep_k(
    const float* __restrict__ x, const float* __restrict__ ln1_g, const float* __restrict__ ln1_b,
    __half* __restrict__ h,
    const float* __restrict__ Wqkv, __half* __restrict__ wqkvT,
    const float* __restrict__ Wproj, __half* __restrict__ wprojT,
    const float* __restrict__ W1, __half* __restrict__ w1T,
    const float* __restrict__ W2, __half* __restrict__ w2T)
{
    __shared__ float tbuf[32][33];
    __shared__ float sh_s[8];
    __shared__ float sh_q[8];

    int bid = blockIdx.x;
    if (bid < BLz) {                               // LN1: 4096 blocks
        dev_ln(x, ln1_g, ln1_b, h, bid, sh_s, sh_q);
        return;
    }
    bid -= BLz;
    if (bid < (E3z / 32) * (Ez / 32)) {            // Wqkv^T: 3072 blocks
        dev_transpose(Wqkv, wqkvT, E3z, Ez, bid % (E3z / 32), bid / (E3z / 32), tbuf);
        return;
    }
    bid -= (E3z / 32) * (Ez / 32);
    if (bid < (Ez / 32) * (Ez / 32)) {             // Wproj^T: 1024 blocks
        dev_transpose(Wproj, wprojT, Ez, Ez, bid % (Ez / 32), bid / (Ez / 32), tbuf);
        return;
    }
    bid -= (Ez / 32) * (Ez / 32);
    if (bid < (FFz / 32) * (Ez / 32)) {            // W1^T: 4096 blocks
        dev_transpose(W1, w1T, FFz, Ez, bid % (FFz / 32), bid / (FFz / 32), tbuf);
        return;
    }
    bid -= (FFz / 32) * (Ez / 32);
    {                                              // W2^T: 4096 blocks
        dev_transpose(W2, w2T, Ez, FFz, bid % (Ez / 32), bid / (Ez / 32), tbuf);
    }
}

// ---------------- LayerNorm (standalone, for LN2) ----------------
__global__ __launch_bounds__(256) void ln_k(
    const float* __restrict__ x, const float* __restrict__ g,
    const float* __restrict__ b, __half* __restrict__ y)
{
    __shared__ float sh_s[8];
    __shared__ float sh_q[8];
    dev_ln(x, g, b, y, blockIdx.x, sh_s, sh_q);
}

// ---------------- driver ----------------
extern "C" void kernel_launch(void* const* d_in, const int* in_sizes, int n_in,
                              void* d_out, int out_size)
{
    (void)in_sizes; (void)n_in; (void)out_size;
    const float* x      = (const float*)d_in[0];
    const float* ln1_g  = (const float*)d_in[1];
    const float* ln1_b  = (const float*)d_in[2];
    const float* W_qkv  = (const float*)d_in[3];
    const float* W_proj = (const float*)d_in[4];
    const float* b_proj = (const float*)d_in[5];
    const float* ln2_g  = (const float*)d_in[6];
    const float* ln2_b  = (const float*)d_in[7];
    const float* W1     = (const float*)d_in[8];
    const float* b1     = (const float*)d_in[9];
    const float* W2     = (const float*)d_in[10];
    const float* b2     = (const float*)d_in[11];
    float* out = (float*)d_out;

    __half *h, *qkv, *att, *ffn, *wqkvT, *wprojT, *w1T, *w2T;
    float *x1;
    cudaGetSymbolAddress((void**)&h,      g_h);
    cudaGetSymbolAddress((void**)&qkv,    g_qkv);
    cudaGetSymbolAddress((void**)&att,    g_att);
    cudaGetSymbolAddress((void**)&x1,     g_x1);
    cudaGetSymbolAddress((void**)&ffn,    g_ffn);
    cudaGetSymbolAddress((void**)&wqkvT,  g_wqkvT);
    cudaGetSymbolAddress((void**)&wprojT, g_wprojT);
    cudaGetSymbolAddress((void**)&w1T,    g_w1T);
    cudaGetSymbolAddress((void**)&w2T,    g_w2T);

    const int SMG = 3 * 2 * 128 * SLDH * 2;            // 110592 bytes (3-stage)
    const int FLASH_SMEM = (128 + 64 + 64) * QLDH * 2; // 36864 bytes
    cudaFuncSetAttribute(mma_gemm<EPI_NONE,      true >, cudaFuncAttributeMaxDynamicSharedMemorySize, SMG);
    cudaFuncSetAttribute(mma_gemm<EPI_BIAS_RES,  false>, cudaFuncAttributeMaxDynamicSharedMemorySize, SMG);
    cudaFuncSetAttribute(mma_gemm<EPI_BIAS_GELU, true >, cudaFuncAttributeMaxDynamicSharedMemorySize, SMG);
    cudaFuncSetAttribute(flash_k, cudaFuncAttributeMaxDynamicSharedMemorySize, FLASH_SMEM);

    // 1. prep: LN1 + all weight transposes, one launch
    const int PREP_BLOCKS = BLz + (E3z / 32) * (Ez / 32) + (Ez / 32) * (Ez / 32)
                          + (FFz / 32) * (Ez / 32) + (Ez / 32) * (FFz / 32);
    prep_k<<<PREP_BLOCKS, 256>>>(x, ln1_g, ln1_b, h,
                                 W_qkv, wqkvT, W_proj, wprojT, W1, w1T, W2, w2T);

    // 2. qkv = fp16(h @ W_qkv)
    mma_gemm<EPI_NONE, true><<<dim3(E3z / 128, BLz / 128, 1), 256, SMG>>>(
        h, wqkvT, qkv, nullptr, nullptr, Ez, Ez, Ez, E3z);

    // 3. att = flash(Q, K, V)  — V straight from qkv via ldmatrix.trans
    flash_k<<<dim3(Lz / 128, Bz * Hz), 256, FLASH_SMEM>>>(qkv, att);

    // 4. x1 = x + att @ W_proj + b_proj   (fp32)
    mma_gemm<EPI_BIAS_RES, false><<<dim3(Ez / 128, BLz / 128, 1), 256, SMG>>>(
        att, wprojT, x1, b_proj, x, Ez, Ez, Ez, Ez);

    // 5. h = fp16(LN2(x1))
    ln_k<<<BLz, 256>>>(x1, ln2_g, ln2_b, h);

    // 6. ffn = fp16(gelu(h @ W1 + b1))
    mma_gemm<EPI_BIAS_GELU, true><<<dim3(FFz / 128, BLz / 128, 1), 256, SMG>>>(
        h, w1T, ffn, b1, nullptr, Ez, Ez, Ez, FFz);

    // 7. out = x1 + ffn @ W2 + b2   (fp32 final output)
    mma_gemm<EPI_BIAS_RES, false><<<dim3(Ez / 128, BLz / 128, 1), 256, SMG>>>(
        ffn, w2T, out, b2, x1, FFz, FFz, FFz, Ez);
}